// round 6
// baseline (speedup 1.0000x reference)
#include <cuda_runtime.h>
#include <math.h>
#include <stdint.h>

#define BATCH 8
#define DIM   512
#define HEADS 8
#define DH    64
#define LSEQ  4096
#define F3    1536            // 3 * HEADS * DIM_HEAD
#define FKV   1024            // k,v thirds only
#define SCALE 0.125f          // DH^-0.5
#define NSPLIT 16

// ---------------- scratch (device globals; no allocation allowed) ----------
__device__ float  g_qkv[(size_t)BATCH * FKV * LSEQ];                 // 134 MB (k,v raw)
__device__ float  g_ctxp[(size_t)BATCH * HEADS * NSPLIT * DH * DH];  // 16.8 MB
__device__ float2 g_stats[(size_t)BATCH * DIM];                      // (max, 1/sumexp)
__device__ float  g_wctxT[(size_t)BATCH * DIM * DIM];                // 8 MB
__device__ float  g_wqT[(size_t)DIM * DIM];                          // 1 MB
__device__ float  g_M2[(size_t)BATCH * DIM * DIM];                   // 8 MB

// ======================= helpers ==========================================
__device__ __forceinline__ uint32_t f2tf32(float x) {
    uint32_t u;
    asm("cvt.rna.tf32.f32 %0, %1;" : "=r"(u) : "f"(x));
    return u;
}

__device__ __forceinline__ void mma_tf32(float c[4], const uint32_t a[4], const uint32_t b[2]) {
    asm volatile(
        "mma.sync.aligned.m16n8k8.row.col.f32.tf32.tf32.f32 "
        "{%0,%1,%2,%3}, {%4,%5,%6,%7}, {%8,%9}, {%0,%1,%2,%3};"
        : "+f"(c[0]), "+f"(c[1]), "+f"(c[2]), "+f"(c[3])
        : "r"(a[0]), "r"(a[1]), "r"(a[2]), "r"(a[3]), "r"(b[0]), "r"(b[1]));
}

// ======================= transpose ========================================
__global__ __launch_bounds__(256) void transpose_k(
    const float* __restrict__ in, float* __restrict__ out,
    int R, int C, int ldin)
{
    __shared__ float t[32][33];
    const int c0 = blockIdx.x * 32;
    const int r0 = blockIdx.y * 32;
    const int tx = threadIdx.x & 31;
    const int ty = threadIdx.x >> 5;
#pragma unroll
    for (int i = 0; i < 4; i++)
        t[ty + i * 8][tx] = in[(long)(r0 + ty + i * 8) * ldin + c0 + tx];
    __syncthreads();
#pragma unroll
    for (int i = 0; i < 4; i++)
        out[(long)(c0 + ty + i * 8) * R + r0 + tx] = t[tx][ty + i * 8];
}

// ======================= tf32 warp-MMA GEMM ================================
// C[m,n] = sum_k A[k,m]*B[k,n] (+bias[m]); A: KxM (lda), B: KxN (ldb).
#define BM 128
#define BN 128
#define BK 16

__global__ __launch_bounds__(256, 2) void gemm_tf32(
    const float* __restrict__ A, const float* __restrict__ B,
    float* __restrict__ C,
    int lda, int ldb, int ldc, int K,
    long sA, long sB, long sC,
    const float* __restrict__ bias)
{
    A += (long)blockIdx.z * sA;
    B += (long)blockIdx.z * sB;
    C += (long)blockIdx.z * sC;

    const int m0 = blockIdx.y * BM;
    const int n0 = blockIdx.x * BN;

    __shared__ uint32_t As[2][BK][BM + 4];
    __shared__ uint32_t Bs[2][BK][BN + 4];

    const int tid  = threadIdx.x;
    const int lane = tid & 31;
    const int g    = lane >> 2;
    const int tg   = lane & 3;
    const int warp = tid >> 5;
    const int wm   = (warp >> 2) * 64;
    const int wn   = (warp & 3) * 32;

    const int srow0 = tid >> 5;
    const int scol0 = (tid & 31) * 4;
    const int srow1 = 8 + (tid >> 5);
    const int scol1 = scol0;

    float c[4][4][4];
#pragma unroll
    for (int i = 0; i < 4; i++)
#pragma unroll
        for (int j = 0; j < 4; j++)
#pragma unroll
            for (int q = 0; q < 4; q++) c[i][j][q] = 0.0f;

    const int ntiles = K / BK;
    float4 pa0, pa1, pb0, pb1;

    pa0 = *reinterpret_cast<const float4*>(&A[(long)srow0 * lda + m0 + scol0]);
    pa1 = *reinterpret_cast<const float4*>(&A[(long)srow1 * lda + m0 + scol1]);
    pb0 = *reinterpret_cast<const float4*>(&B[(long)srow0 * ldb + n0 + scol0]);
    pb1 = *reinterpret_cast<const float4*>(&B[(long)srow1 * ldb + n0 + scol1]);

    int buf = 0;
    {
        uint4 ua0 = {f2tf32(pa0.x), f2tf32(pa0.y), f2tf32(pa0.z), f2tf32(pa0.w)};
        uint4 ua1 = {f2tf32(pa1.x), f2tf32(pa1.y), f2tf32(pa1.z), f2tf32(pa1.w)};
        uint4 ub0 = {f2tf32(pb0.x), f2tf32(pb0.y), f2tf32(pb0.z), f2tf32(pb0.w)};
        uint4 ub1 = {f2tf32(pb1.x), f2tf32(pb1.y), f2tf32(pb1.z), f2tf32(pb1.w)};
        *reinterpret_cast<uint4*>(&As[0][srow0][scol0]) = ua0;
        *reinterpret_cast<uint4*>(&As[0][srow1][scol1]) = ua1;
        *reinterpret_cast<uint4*>(&Bs[0][srow0][scol0]) = ub0;
        *reinterpret_cast<uint4*>(&Bs[0][srow1][scol1]) = ub1;
    }
    __syncthreads();

    for (int kt = 0; kt < ntiles; kt++) {
        const bool has_next = (kt + 1) < ntiles;
        if (has_next) {
            const long kb = (long)(kt + 1) * BK;
            pa0 = *reinterpret_cast<const float4*>(&A[(kb + srow0) * lda + m0 + scol0]);
            pa1 = *reinterpret_cast<const float4*>(&A[(kb + srow1) * lda + m0 + scol1]);
            pb0 = *reinterpret_cast<const float4*>(&B[(kb + srow0) * ldb + n0 + scol0]);
            pb1 = *reinterpret_cast<const float4*>(&B[(kb + srow1) * ldb + n0 + scol1]);
        }

#pragma unroll
        for (int ks = 0; ks < BK; ks += 8) {
            uint32_t af[4][4];
            uint32_t bf[4][2];
#pragma unroll
            for (int mt = 0; mt < 4; mt++) {
                const int mb = wm + mt * 16;
                af[mt][0] = As[buf][ks + tg    ][mb + g];
                af[mt][1] = As[buf][ks + tg    ][mb + g + 8];
                af[mt][2] = As[buf][ks + tg + 4][mb + g];
                af[mt][3] = As[buf][ks + tg + 4][mb + g + 8];
            }
#pragma unroll
            for (int nt = 0; nt < 4; nt++) {
                const int nb = wn + nt * 8;
                bf[nt][0] = Bs[buf][ks + tg    ][nb + g];
                bf[nt][1] = Bs[buf][ks + tg + 4][nb + g];
            }
#pragma unroll
            for (int mt = 0; mt < 4; mt++)
#pragma unroll
                for (int nt = 0; nt < 4; nt++)
                    mma_tf32(c[mt][nt], af[mt], bf[nt]);
        }

        if (has_next) {
            uint4 ua0 = {f2tf32(pa0.x), f2tf32(pa0.y), f2tf32(pa0.z), f2tf32(pa0.w)};
            uint4 ua1 = {f2tf32(pa1.x), f2tf32(pa1.y), f2tf32(pa1.z), f2tf32(pa1.w)};
            uint4 ub0 = {f2tf32(pb0.x), f2tf32(pb0.y), f2tf32(pb0.z), f2tf32(pb0.w)};
            uint4 ub1 = {f2tf32(pb1.x), f2tf32(pb1.y), f2tf32(pb1.z), f2tf32(pb1.w)};
            const int nb = buf ^ 1;
            *reinterpret_cast<uint4*>(&As[nb][srow0][scol0]) = ua0;
            *reinterpret_cast<uint4*>(&As[nb][srow1][scol1]) = ua1;
            *reinterpret_cast<uint4*>(&Bs[nb][srow0][scol0]) = ub0;
            *reinterpret_cast<uint4*>(&Bs[nb][srow1][scol1]) = ub1;
        }
        __syncthreads();
        buf ^= 1;
    }

#pragma unroll
    for (int mt = 0; mt < 4; mt++) {
        const int m = m0 + wm + mt * 16 + g;
        const float bv0 = bias ? bias[m]     : 0.0f;
        const float bv8 = bias ? bias[m + 8] : 0.0f;
#pragma unroll
        for (int nt = 0; nt < 4; nt++) {
            const int n = n0 + wn + nt * 8 + 2 * tg;
            float2 o0 = {c[mt][nt][0] + bv0, c[mt][nt][1] + bv0};
            float2 o1 = {c[mt][nt][2] + bv8, c[mt][nt][3] + bv8};
            *reinterpret_cast<float2*>(&C[(long)m * ldc + n])       = o0;
            *reinterpret_cast<float2*>(&C[(long)(m + 8) * ldc + n]) = o1;
        }
    }
}

// ======================= softmax stats (no write-back) =====================
// Per k-row (b, r): m = max over L, invs = 1/sum(exp(v-m)). 67 MB read only.
__global__ __launch_bounds__(256) void softmax_stats()
{
    const int row = blockIdx.x;           // 0 .. BATCH*DIM-1
    const int b = row / DIM;
    const int r = row % DIM;
    const float* p = g_qkv + (long)b * FKV * LSEQ + (long)r * LSEQ;

    const int tid = threadIdx.x;
    float4 v[4];
    float mx = -1e30f;
#pragma unroll
    for (int i = 0; i < 4; i++) {
        v[i] = reinterpret_cast<const float4*>(p)[tid + i * 256];
        mx = fmaxf(mx, fmaxf(fmaxf(v[i].x, v[i].y), fmaxf(v[i].z, v[i].w)));
    }

    __shared__ float red[8];
#pragma unroll
    for (int o = 16; o; o >>= 1) mx = fmaxf(mx, __shfl_xor_sync(~0u, mx, o));
    if ((tid & 31) == 0) red[tid >> 5] = mx;
    __syncthreads();
    mx = red[0];
#pragma unroll
    for (int i = 1; i < 8; i++) mx = fmaxf(mx, red[i]);
    __syncthreads();

    float s = 0.0f;
#pragma unroll
    for (int i = 0; i < 4; i++) {
        s += expf(v[i].x - mx) + expf(v[i].y - mx)
           + expf(v[i].z - mx) + expf(v[i].w - mx);
    }
#pragma unroll
    for (int o = 16; o; o >>= 1) s += __shfl_xor_sync(~0u, s, o);
    if ((tid & 31) == 0) red[tid >> 5] = s;
    __syncthreads();
    if (tid == 0) {
        s = red[0];
#pragma unroll
        for (int i = 1; i < 8; i++) s += red[i];
        g_stats[row] = make_float2(mx, 1.0f / s);
    }
}

// ======================= ctx partials: tensor cores + fused softmax ========
// partial[d,e] = invs[d] * sum_{n in slice} exp(K[d,n]-m[d]) * V[e,n]
// Block: one (bh, split); M=64(d) x N=64(e) x 256(n) in chunks of 32.
// Warps 2x4 (warp tile 32x16), mma m16n8k8 tf32, fragment maps verified in R2.
#define CP 72   // smem row stride (words): bank-conflict-free fragment loads
__global__ __launch_bounds__(256) void ctx_partial_tc()
{
    const int bh = blockIdx.x;                 // 0..63
    const int split = blockIdx.y;              // 0..NSPLIT-1
    const int b = bh >> 3, h = bh & 7;
    const float* Kp = g_qkv + (long)b * FKV * LSEQ + (long)(h * DH) * LSEQ;
    const float* Vp = g_qkv + (long)b * FKV * LSEQ + (long)(DIM + h * DH) * LSEQ;
    const int n0 = split * (LSEQ / NSPLIT);    // 256 per slice

    __shared__ uint32_t Ks[32][CP];            // [n'][d]
    __shared__ uint32_t Vs[32][CP];            // [n'][e]

    const int tid  = threadIdx.x;
    const int lane = tid & 31;
    const int g    = lane >> 2;
    const int tg   = lane & 3;
    const int warp = tid >> 5;
    const int wm   = (warp >> 2) * 32;
    const int wn   = (warp & 3) * 16;

    // staging map: thread handles row r, n-cols [q*8, q*8+8)
    const int r = tid >> 2;                    // 0..63
    const int q = tid & 3;                     // 0..3
    const float m_r = g_stats[b * DIM + h * DH + r].x;

    float acc[2][2][4];
#pragma unroll
    for (int i = 0; i < 2; i++)
#pragma unroll
        for (int j = 0; j < 2; j++)
#pragma unroll
            for (int p = 0; p < 4; p++) acc[i][j][p] = 0.0f;

    float4 k0, k1, v0, v1;
    const float* kr = Kp + (long)r * LSEQ + n0 + q * 8;
    const float* vr = Vp + (long)r * LSEQ + n0 + q * 8;
    k0 = *reinterpret_cast<const float4*>(kr);
    k1 = *reinterpret_cast<const float4*>(kr + 4);
    v0 = *reinterpret_cast<const float4*>(vr);
    v1 = *reinterpret_cast<const float4*>(vr + 4);

    for (int c = 0; c < 8; c++) {
        // store staged chunk (exp for K, tf32 round both)
        const int nb = q * 8;
        Ks[nb    ][r] = f2tf32(expf(k0.x - m_r));
        Ks[nb + 1][r] = f2tf32(expf(k0.y - m_r));
        Ks[nb + 2][r] = f2tf32(expf(k0.z - m_r));
        Ks[nb + 3][r] = f2tf32(expf(k0.w - m_r));
        Ks[nb + 4][r] = f2tf32(expf(k1.x - m_r));
        Ks[nb + 5][r] = f2tf32(expf(k1.y - m_r));
        Ks[nb + 6][r] = f2tf32(expf(k1.z - m_r));
        Ks[nb + 7][r] = f2tf32(expf(k1.w - m_r));
        Vs[nb    ][r] = f2tf32(v0.x);
        Vs[nb + 1][r] = f2tf32(v0.y);
        Vs[nb + 2][r] = f2tf32(v0.z);
        Vs[nb + 3][r] = f2tf32(v0.w);
        Vs[nb + 4][r] = f2tf32(v1.x);
        Vs[nb + 5][r] = f2tf32(v1.y);
        Vs[nb + 6][r] = f2tf32(v1.z);
        Vs[nb + 7][r] = f2tf32(v1.w);
        __syncthreads();

        if (c + 1 < 8) {
            const float* krn = kr + (c + 1) * 32;
            const float* vrn = vr + (c + 1) * 32;
            k0 = *reinterpret_cast<const float4*>(krn);
            k1 = *reinterpret_cast<const float4*>(krn + 4);
            v0 = *reinterpret_cast<const float4*>(vrn);
            v1 = *reinterpret_cast<const float4*>(vrn + 4);
        }

#pragma unroll
        for (int ks = 0; ks < 32; ks += 8) {
            uint32_t af[2][4];
            uint32_t bf[2][2];
#pragma unroll
            for (int mt = 0; mt < 2; mt++) {
                const int mb = wm + mt * 16;
                af[mt][0] = Ks[ks + tg    ][mb + g];
                af[mt][1] = Ks[ks + tg    ][mb + g + 8];
                af[mt][2] = Ks[ks + tg + 4][mb + g];
                af[mt][3] = Ks[ks + tg + 4][mb + g + 8];
            }
#pragma unroll
            for (int nt = 0; nt < 2; nt++) {
                const int nbx = wn + nt * 8;
                bf[nt][0] = Vs[ks + tg    ][nbx + g];
                bf[nt][1] = Vs[ks + tg + 4][nbx + g];
            }
#pragma unroll
            for (int mt = 0; mt < 2; mt++)
#pragma unroll
                for (int nt = 0; nt < 2; nt++)
                    mma_tf32(acc[mt][nt], af[mt], bf[nt]);
        }
        __syncthreads();
    }

    // epilogue: scale rows by invs and write partial
    float* cp = g_ctxp + ((long)bh * NSPLIT + split) * DH * DH;
#pragma unroll
    for (int mt = 0; mt < 2; mt++) {
        const int m = wm + mt * 16 + g;
        const float is0 = g_stats[b * DIM + h * DH + m].y;
        const float is8 = g_stats[b * DIM + h * DH + m + 8].y;
#pragma unroll
        for (int nt = 0; nt < 2; nt++) {
            const int n = wn + nt * 8 + 2 * tg;
            float2 o0 = {acc[mt][nt][0] * is0, acc[mt][nt][1] * is0};
            float2 o1 = {acc[mt][nt][2] * is8, acc[mt][nt][3] * is8};
            *reinterpret_cast<float2*>(&cp[(long)m * DH + n])       = o0;
            *reinterpret_cast<float2*>(&cp[(long)(m + 8) * DH + n]) = o1;
        }
    }
}

// ======================= fold w_out into ctx (with inline split-reduce) ====
// WctxT[b][(h,d)][c] = SCALE * sum_e ctx[b,h][d,e]*w_out[h*64+e][c]
__global__ __launch_bounds__(256) void wctx_fold(const float* __restrict__ w_out)
{
    const int bh = blockIdx.x;
    const int b = bh / HEADS, h = bh % HEADS;
    __shared__ float cs[64][65];
    const int tid = threadIdx.x;

    const float* cp = g_ctxp + (long)bh * NSPLIT * DH * DH;
    for (int i = tid; i < DH * DH; i += 256) {
        float s = 0.0f;
#pragma unroll
        for (int sp = 0; sp < NSPLIT; sp++)
            s += cp[(long)sp * DH * DH + i];
        cs[i >> 6][i & 63] = s;
    }
    __syncthreads();

    float* outp = g_wctxT + (long)b * DIM * DIM + (long)(h * DH) * DIM;

    for (int cb = 0; cb < 2; cb++) {
        const int c = cb * 256 + tid;
        float w[64];
#pragma unroll
        for (int e = 0; e < 64; e++) w[e] = w_out[(h * DH + e) * DIM + c];
#pragma unroll 4
        for (int d = 0; d < 64; d++) {
            float s = 0.0f;
#pragma unroll
            for (int e = 0; e < 64; e++) s = fmaf(cs[d][e], w[e], s);
            outp[(long)d * DIM + c] = s * SCALE;
        }
    }
}

// ---------------------------------------------------------------------------
extern "C" void kernel_launch(void* const* d_in, const int* in_sizes, int n_in,
                              void* d_out, int out_size)
{
    const float* x      = (const float*)d_in[0];   // (B, 512, 4096)
    const float* w_qkv  = (const float*)d_in[1];   // (512, 1536)
    const float* w_out  = (const float*)d_in[2];   // (512, 512)
    const float* b_out  = (const float*)d_in[3];   // (512,)
    float* out = (float*)d_out;                    // (B, 512, 4096)

    float* qkv;
    float* wctxT;
    float* wqT;
    float* M2;
    cudaGetSymbolAddress((void**)&qkv,   g_qkv);
    cudaGetSymbolAddress((void**)&wctxT, g_wctxT);
    cudaGetSymbolAddress((void**)&wqT,   g_wqT);
    cudaGetSymbolAddress((void**)&M2,    g_M2);

    // 0) wqT[f][cin] = w_qkv[cin][f] for f in [0,512) (q slice)
    {
        dim3 g(DIM / 32, DIM / 32, 1);
        transpose_k<<<g, 256>>>(w_qkv, wqT, DIM, DIM, F3);
    }

    // 1) k,v = W_kv^T @ x per batch
    {
        dim3 grid(LSEQ / BN, FKV / BM, BATCH);
        gemm_tf32<<<grid, 256>>>(w_qkv + DIM, x, qkv,
                                 F3, LSEQ, LSEQ, DIM,
                                 0L, (long)DIM * LSEQ, (long)FKV * LSEQ,
                                 nullptr);
    }

    // 2) softmax stats (max, 1/sumexp) per k row — no write-back
    softmax_stats<<<BATCH * DIM, 256>>>();

    // 3) ctx partials via tensor cores with fused exp/normalize
    {
        dim3 grid(BATCH * HEADS, NSPLIT);
        ctx_partial_tc<<<grid, 256>>>();
    }

    // 4) fold w_out into ctx (reduces partials inline, includes SCALE)
    wctx_fold<<<BATCH * HEADS, 256>>>(w_out);

    // 5) M2[b][cin][c] = sum_f wqT[f][cin] * wctxT[b][f][c]
    {
        dim3 grid(DIM / BN, DIM / BM, BATCH);
        gemm_tf32<<<grid, 256>>>(wqT, wctxT, M2,
                                 DIM, DIM, DIM, DIM,
                                 0L, (long)DIM * DIM, (long)DIM * DIM,
                                 nullptr);
    }

    // 6) out[b][c][l] = sum_cin M2[b][cin][c] * x[b][cin][l] + b_out[c]
    {
        dim3 grid(LSEQ / BN, DIM / BM, BATCH);
        gemm_tf32<<<grid, 256>>>(M2, x, out,
                                 DIM, LSEQ, LSEQ, DIM,
                                 (long)DIM * DIM, (long)DIM * LSEQ, (long)DIM * LSEQ,
                                 b_out);
    }
}

// round 8
// speedup vs baseline: 1.5423x; 1.5423x over previous
#include <cuda_runtime.h>
#include <math.h>
#include <stdint.h>

#define BATCH 8
#define DIM   512
#define HEADS 8
#define DH    64
#define LSEQ  4096
#define F3    1536            // 3 * HEADS * DIM_HEAD
#define FKV   1024            // k,v thirds only
#define SCALE 0.125f          // DH^-0.5
#define NSPLIT 16

// ---------------- scratch (device globals; no allocation allowed) ----------
__device__ float  g_qkv[(size_t)BATCH * FKV * LSEQ];                 // 134 MB (k,v raw)
__device__ float  g_ctxp[(size_t)BATCH * HEADS * NSPLIT * DH * DH];  // 16.8 MB
__device__ float  g_ctx[(size_t)BATCH * HEADS * DH * DH];            // 1 MB
__device__ float2 g_stats[(size_t)BATCH * DIM];                      // (max, 1/sumexp)
__device__ float  g_wctxT[(size_t)BATCH * DIM * DIM];                // 8 MB
__device__ float  g_wqT[(size_t)DIM * DIM];                          // 1 MB
__device__ float  g_M2[(size_t)BATCH * DIM * DIM];                   // 8 MB

// ======================= helpers ==========================================
__device__ __forceinline__ uint32_t f2tf32(float x) {
    uint32_t u;
    asm("cvt.rna.tf32.f32 %0, %1;" : "=r"(u) : "f"(x));
    return u;
}

__device__ __forceinline__ void mma_tf32(float c[4], const uint32_t a[4], const uint32_t b[2]) {
    asm volatile(
        "mma.sync.aligned.m16n8k8.row.col.f32.tf32.tf32.f32 "
        "{%0,%1,%2,%3}, {%4,%5,%6,%7}, {%8,%9}, {%0,%1,%2,%3};"
        : "+f"(c[0]), "+f"(c[1]), "+f"(c[2]), "+f"(c[3])
        : "r"(a[0]), "r"(a[1]), "r"(a[2]), "r"(a[3]), "r"(b[0]), "r"(b[1]));
}

// ======================= transpose ========================================
__global__ __launch_bounds__(256) void transpose_k(
    const float* __restrict__ in, float* __restrict__ out,
    int R, int C, int ldin)
{
    __shared__ float t[32][33];
    const int c0 = blockIdx.x * 32;
    const int r0 = blockIdx.y * 32;
    const int tx = threadIdx.x & 31;
    const int ty = threadIdx.x >> 5;
#pragma unroll
    for (int i = 0; i < 4; i++)
        t[ty + i * 8][tx] = in[(long)(r0 + ty + i * 8) * ldin + c0 + tx];
    __syncthreads();
#pragma unroll
    for (int i = 0; i < 4; i++)
        out[(long)(c0 + ty + i * 8) * R + r0 + tx] = t[tx][ty + i * 8];
}

// ======================= tf32 warp-MMA GEMM ================================
// C[m,n] = sum_k A[k,m]*B[k,n] (+bias[m]); A: KxM (lda), B: KxN (ldb).
#define BM 128
#define BN 128
#define BK 16

__global__ __launch_bounds__(256, 2) void gemm_tf32(
    const float* __restrict__ A, const float* __restrict__ B,
    float* __restrict__ C,
    int lda, int ldb, int ldc, int K,
    long sA, long sB, long sC,
    const float* __restrict__ bias)
{
    A += (long)blockIdx.z * sA;
    B += (long)blockIdx.z * sB;
    C += (long)blockIdx.z * sC;

    const int m0 = blockIdx.y * BM;
    const int n0 = blockIdx.x * BN;

    __shared__ uint32_t As[2][BK][BM + 4];
    __shared__ uint32_t Bs[2][BK][BN + 4];

    const int tid  = threadIdx.x;
    const int lane = tid & 31;
    const int g    = lane >> 2;
    const int tg   = lane & 3;
    const int warp = tid >> 5;
    const int wm   = (warp >> 2) * 64;
    const int wn   = (warp & 3) * 32;

    const int srow0 = tid >> 5;
    const int scol0 = (tid & 31) * 4;
    const int srow1 = 8 + (tid >> 5);
    const int scol1 = scol0;

    float c[4][4][4];
#pragma unroll
    for (int i = 0; i < 4; i++)
#pragma unroll
        for (int j = 0; j < 4; j++)
#pragma unroll
            for (int q = 0; q < 4; q++) c[i][j][q] = 0.0f;

    const int ntiles = K / BK;
    float4 pa0, pa1, pb0, pb1;

    pa0 = *reinterpret_cast<const float4*>(&A[(long)srow0 * lda + m0 + scol0]);
    pa1 = *reinterpret_cast<const float4*>(&A[(long)srow1 * lda + m0 + scol1]);
    pb0 = *reinterpret_cast<const float4*>(&B[(long)srow0 * ldb + n0 + scol0]);
    pb1 = *reinterpret_cast<const float4*>(&B[(long)srow1 * ldb + n0 + scol1]);

    int buf = 0;
    {
        uint4 ua0 = {f2tf32(pa0.x), f2tf32(pa0.y), f2tf32(pa0.z), f2tf32(pa0.w)};
        uint4 ua1 = {f2tf32(pa1.x), f2tf32(pa1.y), f2tf32(pa1.z), f2tf32(pa1.w)};
        uint4 ub0 = {f2tf32(pb0.x), f2tf32(pb0.y), f2tf32(pb0.z), f2tf32(pb0.w)};
        uint4 ub1 = {f2tf32(pb1.x), f2tf32(pb1.y), f2tf32(pb1.z), f2tf32(pb1.w)};
        *reinterpret_cast<uint4*>(&As[0][srow0][scol0]) = ua0;
        *reinterpret_cast<uint4*>(&As[0][srow1][scol1]) = ua1;
        *reinterpret_cast<uint4*>(&Bs[0][srow0][scol0]) = ub0;
        *reinterpret_cast<uint4*>(&Bs[0][srow1][scol1]) = ub1;
    }
    __syncthreads();

    for (int kt = 0; kt < ntiles; kt++) {
        const bool has_next = (kt + 1) < ntiles;
        if (has_next) {
            const long kb = (long)(kt + 1) * BK;
            pa0 = *reinterpret_cast<const float4*>(&A[(kb + srow0) * lda + m0 + scol0]);
            pa1 = *reinterpret_cast<const float4*>(&A[(kb + srow1) * lda + m0 + scol1]);
            pb0 = *reinterpret_cast<const float4*>(&B[(kb + srow0) * ldb + n0 + scol0]);
            pb1 = *reinterpret_cast<const float4*>(&B[(kb + srow1) * ldb + n0 + scol1]);
        }

#pragma unroll
        for (int ks = 0; ks < BK; ks += 8) {
            uint32_t af[4][4];
            uint32_t bf[4][2];
#pragma unroll
            for (int mt = 0; mt < 4; mt++) {
                const int mb = wm + mt * 16;
                af[mt][0] = As[buf][ks + tg    ][mb + g];
                af[mt][1] = As[buf][ks + tg    ][mb + g + 8];
                af[mt][2] = As[buf][ks + tg + 4][mb + g];
                af[mt][3] = As[buf][ks + tg + 4][mb + g + 8];
            }
#pragma unroll
            for (int nt = 0; nt < 4; nt++) {
                const int nb = wn + nt * 8;
                bf[nt][0] = Bs[buf][ks + tg    ][nb + g];
                bf[nt][1] = Bs[buf][ks + tg + 4][nb + g];
            }
#pragma unroll
            for (int mt = 0; mt < 4; mt++)
#pragma unroll
                for (int nt = 0; nt < 4; nt++)
                    mma_tf32(c[mt][nt], af[mt], bf[nt]);
        }

        if (has_next) {
            uint4 ua0 = {f2tf32(pa0.x), f2tf32(pa0.y), f2tf32(pa0.z), f2tf32(pa0.w)};
            uint4 ua1 = {f2tf32(pa1.x), f2tf32(pa1.y), f2tf32(pa1.z), f2tf32(pa1.w)};
            uint4 ub0 = {f2tf32(pb0.x), f2tf32(pb0.y), f2tf32(pb0.z), f2tf32(pb0.w)};
            uint4 ub1 = {f2tf32(pb1.x), f2tf32(pb1.y), f2tf32(pb1.z), f2tf32(pb1.w)};
            const int nb = buf ^ 1;
            *reinterpret_cast<uint4*>(&As[nb][srow0][scol0]) = ua0;
            *reinterpret_cast<uint4*>(&As[nb][srow1][scol1]) = ua1;
            *reinterpret_cast<uint4*>(&Bs[nb][srow0][scol0]) = ub0;
            *reinterpret_cast<uint4*>(&Bs[nb][srow1][scol1]) = ub1;
        }
        __syncthreads();
        buf ^= 1;
    }

#pragma unroll
    for (int mt = 0; mt < 4; mt++) {
        const int m = m0 + wm + mt * 16 + g;
        const float bv0 = bias ? bias[m]     : 0.0f;
        const float bv8 = bias ? bias[m + 8] : 0.0f;
#pragma unroll
        for (int nt = 0; nt < 4; nt++) {
            const int n = n0 + wn + nt * 8 + 2 * tg;
            float2 o0 = {c[mt][nt][0] + bv0, c[mt][nt][1] + bv0};
            float2 o1 = {c[mt][nt][2] + bv8, c[mt][nt][3] + bv8};
            *reinterpret_cast<float2*>(&C[(long)m * ldc + n])       = o0;
            *reinterpret_cast<float2*>(&C[(long)(m + 8) * ldc + n]) = o1;
        }
    }
}

// ======================= softmax stats (no write-back) =====================
__global__ __launch_bounds__(256) void softmax_stats()
{
    const int row = blockIdx.x;           // 0 .. BATCH*DIM-1
    const int b = row / DIM;
    const int r = row % DIM;
    const float* p = g_qkv + (long)b * FKV * LSEQ + (long)r * LSEQ;

    const int tid = threadIdx.x;
    float4 v[4];
    float mx = -1e30f;
#pragma unroll
    for (int i = 0; i < 4; i++) {
        v[i] = reinterpret_cast<const float4*>(p)[tid + i * 256];
        mx = fmaxf(mx, fmaxf(fmaxf(v[i].x, v[i].y), fmaxf(v[i].z, v[i].w)));
    }

    __shared__ float red[8];
#pragma unroll
    for (int o = 16; o; o >>= 1) mx = fmaxf(mx, __shfl_xor_sync(~0u, mx, o));
    if ((tid & 31) == 0) red[tid >> 5] = mx;
    __syncthreads();
    mx = red[0];
#pragma unroll
    for (int i = 1; i < 8; i++) mx = fmaxf(mx, red[i]);
    __syncthreads();

    float s = 0.0f;
#pragma unroll
    for (int i = 0; i < 4; i++) {
        s += expf(v[i].x - mx) + expf(v[i].y - mx)
           + expf(v[i].z - mx) + expf(v[i].w - mx);
    }
#pragma unroll
    for (int o = 16; o; o >>= 1) s += __shfl_xor_sync(~0u, s, o);
    if ((tid & 31) == 0) red[tid >> 5] = s;
    __syncthreads();
    if (tid == 0) {
        s = red[0];
#pragma unroll
        for (int i = 1; i < 8; i++) s += red[i];
        g_stats[row] = make_float2(mx, 1.0f / s);
    }
}

// ======================= ctx partials: tensor cores + fused softmax ========
// partial[d,e] = invs[d] * sum_{n in slice} exp(K[d,n]-m[d]) * V[e,n]
#define CP 72   // smem row stride (words)
__global__ __launch_bounds__(256) void ctx_partial_tc()
{
    const int bh = blockIdx.x;                 // 0..63
    const int split = blockIdx.y;              // 0..NSPLIT-1
    const int b = bh >> 3, h = bh & 7;
    const float* Kp = g_qkv + (long)b * FKV * LSEQ + (long)(h * DH) * LSEQ;
    const float* Vp = g_qkv + (long)b * FKV * LSEQ + (long)(DIM + h * DH) * LSEQ;
    const int n0 = split * (LSEQ / NSPLIT);    // 256 per slice

    __shared__ uint32_t Ks[32][CP];            // [n'][d]
    __shared__ uint32_t Vs[32][CP];            // [n'][e]

    const int tid  = threadIdx.x;
    const int lane = tid & 31;
    const int g    = lane >> 2;
    const int tg   = lane & 3;
    const int warp = tid >> 5;
    const int wm   = (warp >> 2) * 32;
    const int wn   = (warp & 3) * 16;

    const int r = tid >> 2;                    // 0..63
    const int q = tid & 3;                     // 0..3
    const float m_r = g_stats[b * DIM + h * DH + r].x;

    float acc[2][2][4];
#pragma unroll
    for (int i = 0; i < 2; i++)
#pragma unroll
        for (int j = 0; j < 2; j++)
#pragma unroll
            for (int p = 0; p < 4; p++) acc[i][j][p] = 0.0f;

    float4 k0, k1, v0, v1;
    const float* kr = Kp + (long)r * LSEQ + n0 + q * 8;
    const float* vr = Vp + (long)r * LSEQ + n0 + q * 8;
    k0 = *reinterpret_cast<const float4*>(kr);
    k1 = *reinterpret_cast<const float4*>(kr + 4);
    v0 = *reinterpret_cast<const float4*>(vr);
    v1 = *reinterpret_cast<const float4*>(vr + 4);

    for (int c = 0; c < 8; c++) {
        const int nb = q * 8;
        Ks[nb    ][r] = f2tf32(expf(k0.x - m_r));
        Ks[nb + 1][r] = f2tf32(expf(k0.y - m_r));
        Ks[nb + 2][r] = f2tf32(expf(k0.z - m_r));
        Ks[nb + 3][r] = f2tf32(expf(k0.w - m_r));
        Ks[nb + 4][r] = f2tf32(expf(k1.x - m_r));
        Ks[nb + 5][r] = f2tf32(expf(k1.y - m_r));
        Ks[nb + 6][r] = f2tf32(expf(k1.z - m_r));
        Ks[nb + 7][r] = f2tf32(expf(k1.w - m_r));
        Vs[nb    ][r] = f2tf32(v0.x);
        Vs[nb + 1][r] = f2tf32(v0.y);
        Vs[nb + 2][r] = f2tf32(v0.z);
        Vs[nb + 3][r] = f2tf32(v0.w);
        Vs[nb + 4][r] = f2tf32(v1.x);
        Vs[nb + 5][r] = f2tf32(v1.y);
        Vs[nb + 6][r] = f2tf32(v1.z);
        Vs[nb + 7][r] = f2tf32(v1.w);
        __syncthreads();

        if (c + 1 < 8) {
            const float* krn = kr + (c + 1) * 32;
            const float* vrn = vr + (c + 1) * 32;
            k0 = *reinterpret_cast<const float4*>(krn);
            k1 = *reinterpret_cast<const float4*>(krn + 4);
            v0 = *reinterpret_cast<const float4*>(vrn);
            v1 = *reinterpret_cast<const float4*>(vrn + 4);
        }

#pragma unroll
        for (int ks = 0; ks < 32; ks += 8) {
            uint32_t af[2][4];
            uint32_t bf[2][2];
#pragma unroll
            for (int mt = 0; mt < 2; mt++) {
                const int mb = wm + mt * 16;
                af[mt][0] = Ks[ks + tg    ][mb + g];
                af[mt][1] = Ks[ks + tg    ][mb + g + 8];
                af[mt][2] = Ks[ks + tg + 4][mb + g];
                af[mt][3] = Ks[ks + tg + 4][mb + g + 8];
            }
#pragma unroll
            for (int nt = 0; nt < 2; nt++) {
                const int nbx = wn + nt * 8;
                bf[nt][0] = Vs[ks + tg    ][nbx + g];
                bf[nt][1] = Vs[ks + tg + 4][nbx + g];
            }
#pragma unroll
            for (int mt = 0; mt < 2; mt++)
#pragma unroll
                for (int nt = 0; nt < 2; nt++)
                    mma_tf32(acc[mt][nt], af[mt], bf[nt]);
        }
        __syncthreads();
    }

    float* cp = g_ctxp + ((long)bh * NSPLIT + split) * DH * DH;
#pragma unroll
    for (int mt = 0; mt < 2; mt++) {
        const int m = wm + mt * 16 + g;
        const float is0 = g_stats[b * DIM + h * DH + m].y;
        const float is8 = g_stats[b * DIM + h * DH + m + 8].y;
#pragma unroll
        for (int nt = 0; nt < 2; nt++) {
            const int n = wn + nt * 8 + 2 * tg;
            float2 o0 = {acc[mt][nt][0] * is0, acc[mt][nt][1] * is0};
            float2 o1 = {acc[mt][nt][2] * is8, acc[mt][nt][3] * is8};
            *reinterpret_cast<float2*>(&cp[(long)m * DH + n])       = o0;
            *reinterpret_cast<float2*>(&cp[(long)(m + 8) * DH + n]) = o1;
        }
    }
}

// ======================= parallel split reduce =============================
__global__ __launch_bounds__(256) void ctx_reduce()
{
    const int idx = blockIdx.x * 256 + threadIdx.x;   // 0 .. 64*4096-1
    const int bh = idx >> 12;
    const int i  = idx & 4095;
    float s = 0.0f;
#pragma unroll
    for (int sp = 0; sp < NSPLIT; sp++)
        s += g_ctxp[((long)bh * NSPLIT + sp) * DH * DH + i];
    g_ctx[(long)bh * DH * DH + i] = s;
}

// ======================= fold w_out into ctx ===============================
// WctxT[b][(h,d)][c] = SCALE * sum_e ctx[b,h][d,e]*w_out[h*64+e][c]
__global__ __launch_bounds__(256) void wctx_fold(const float* __restrict__ w_out)
{
    const int bh = blockIdx.x;
    const int b = bh / HEADS, h = bh % HEADS;
    __shared__ float cs[64][65];
    const int tid = threadIdx.x;

    const float* cp = g_ctx + (long)bh * DH * DH;
    for (int i = tid; i < DH * DH; i += 256) cs[i >> 6][i & 63] = cp[i];
    __syncthreads();

    float* outp = g_wctxT + (long)b * DIM * DIM + (long)(h * DH) * DIM;

    for (int cb = 0; cb < 2; cb++) {
        const int c = cb * 256 + tid;
        float w[64];
#pragma unroll
        for (int e = 0; e < 64; e++) w[e] = w_out[(h * DH + e) * DIM + c];
#pragma unroll 4
        for (int d = 0; d < 64; d++) {
            float s = 0.0f;
#pragma unroll
            for (int e = 0; e < 64; e++) s = fmaf(cs[d][e], w[e], s);
            outp[(long)d * DIM + c] = s * SCALE;
        }
    }
}

// ---------------------------------------------------------------------------
extern "C" void kernel_launch(void* const* d_in, const int* in_sizes, int n_in,
                              void* d_out, int out_size)
{
    const float* x      = (const float*)d_in[0];   // (B, 512, 4096)
    const float* w_qkv  = (const float*)d_in[1];   // (512, 1536)
    const float* w_out  = (const float*)d_in[2];   // (512, 512)
    const float* b_out  = (const float*)d_in[3];   // (512,)
    float* out = (float*)d_out;                    // (B, 512, 4096)

    float* qkv;
    float* wctxT;
    float* wqT;
    float* M2;
    cudaGetSymbolAddress((void**)&qkv,   g_qkv);
    cudaGetSymbolAddress((void**)&wctxT, g_wctxT);
    cudaGetSymbolAddress((void**)&wqT,   g_wqT);
    cudaGetSymbolAddress((void**)&M2,    g_M2);

    // 0) wqT[f][cin] = w_qkv[cin][f] for f in [0,512) (q slice)
    {
        dim3 g(DIM / 32, DIM / 32, 1);
        transpose_k<<<g, 256>>>(w_qkv, wqT, DIM, DIM, F3);
    }

    // 1) k,v = W_kv^T @ x per batch
    {
        dim3 grid(LSEQ / BN, FKV / BM, BATCH);
        gemm_tf32<<<grid, 256>>>(w_qkv + DIM, x, qkv,
                                 F3, LSEQ, LSEQ, DIM,
                                 0L, (long)DIM * LSEQ, (long)FKV * LSEQ,
                                 nullptr);
    }

    // 2) softmax stats (max, 1/sumexp) per k row — no write-back
    softmax_stats<<<BATCH * DIM, 256>>>();

    // 3) ctx partials via tensor cores with fused exp/normalize
    {
        dim3 grid(BATCH * HEADS, NSPLIT);
        ctx_partial_tc<<<grid, 256>>>();
    }

    // 3b) parallel reduce of partials (1024 CTAs — keeps the chip full)
    ctx_reduce<<<(BATCH * HEADS * DH * DH) / 256, 256>>>();

    // 4) fold w_out into ctx (includes SCALE)
    wctx_fold<<<BATCH * HEADS, 256>>>(w_out);

    // 5) M2[b][cin][c] = sum_f wqT[f][cin] * wctxT[b][f][c]
    {
        dim3 grid(DIM / BN, DIM / BM, BATCH);
        gemm_tf32<<<grid, 256>>>(wqT, wctxT, M2,
                                 DIM, DIM, DIM, DIM,
                                 0L, (long)DIM * DIM, (long)DIM * DIM,
                                 nullptr);
    }

    // 6) out[b][c][l] = sum_cin M2[b][cin][c] * x[b][cin][l] + b_out[c]
    {
        dim3 grid(LSEQ / BN, DIM / BM, BATCH);
        gemm_tf32<<<grid, 256>>>(M2, x, out,
                                 DIM, LSEQ, LSEQ, DIM,
                                 (long)DIM * DIM, (long)DIM * LSEQ, (long)DIM * LSEQ,
                                 b_out);
    }
}

// round 9
// speedup vs baseline: 1.7470x; 1.1327x over previous
#include <cuda_runtime.h>
#include <math.h>
#include <stdint.h>

#define BATCH 8
#define DIM   512
#define HEADS 8
#define DH    64
#define LSEQ  4096
#define F3    1536            // 3 * HEADS * DIM_HEAD
#define FKV   1024            // k,v thirds only
#define SCALE 0.125f          // DH^-0.5
#define NSPLIT 16

// ---------------- scratch (device globals; no allocation allowed) ----------
__device__ float  g_qkv[(size_t)BATCH * FKV * LSEQ];                 // 134 MB (k,v raw)
__device__ float  g_xr[(size_t)BATCH * DIM * LSEQ];                  // 67 MB (x, RNA-rounded)
__device__ float  g_wkv[(size_t)DIM * FKV];                          // 2 MB (w kv slice, RNA)
__device__ float  g_ctxp[(size_t)BATCH * HEADS * NSPLIT * DH * DH];  // 16.8 MB
__device__ float  g_ctx[(size_t)BATCH * HEADS * DH * DH];            // 1 MB
__device__ float2 g_stats[(size_t)BATCH * DIM];                      // (max, 1/sumexp)
__device__ float  g_wctxT[(size_t)BATCH * DIM * DIM];                // 8 MB
__device__ float  g_wqT[(size_t)DIM * DIM];                          // 1 MB
__device__ float  g_M2[(size_t)BATCH * DIM * DIM];                   // 8 MB (RNA-rounded)

// ======================= helpers ==========================================
__device__ __forceinline__ uint32_t f2tf32(float x) {
    uint32_t u;
    asm("cvt.rna.tf32.f32 %0, %1;" : "=r"(u) : "f"(x));
    return u;
}

__device__ __forceinline__ void mma_tf32(float c[4], const uint32_t a[4], const uint32_t b[2]) {
    asm volatile(
        "mma.sync.aligned.m16n8k8.row.col.f32.tf32.tf32.f32 "
        "{%0,%1,%2,%3}, {%4,%5,%6,%7}, {%8,%9}, {%0,%1,%2,%3};"
        : "+f"(c[0]), "+f"(c[1]), "+f"(c[2]), "+f"(c[3])
        : "r"(a[0]), "r"(a[1]), "r"(a[2]), "r"(a[3]), "r"(b[0]), "r"(b[1]));
}

__device__ __forceinline__ uint32_t smem_u32(const void* p) {
    uint32_t a;
    asm("{ .reg .u64 t; cvta.to.shared.u64 t, %1; cvt.u32.u64 %0, t; }" : "=r"(a) : "l"(p));
    return a;
}
__device__ __forceinline__ void cp16(uint32_t dst, const void* src) {
    asm volatile("cp.async.cg.shared.global [%0], [%1], 16;" :: "r"(dst), "l"(src));
}

// ======================= RNA pre-rounding passes ===========================
__global__ __launch_bounds__(256) void rna_vec(const float4* __restrict__ in,
                                               float4* __restrict__ out, int n4)
{
    const int i = blockIdx.x * 256 + threadIdx.x;
    if (i < n4) {
        float4 v = in[i];
        v.x = __uint_as_float(f2tf32(v.x));
        v.y = __uint_as_float(f2tf32(v.y));
        v.z = __uint_as_float(f2tf32(v.z));
        v.w = __uint_as_float(f2tf32(v.w));
        out[i] = v;
    }
}

// copy+round w_qkv columns [512,1536) into contiguous (512 x 1024)
__global__ __launch_bounds__(256) void rna_wkv(const float* __restrict__ w)
{
    const int i = blockIdx.x * 256 + threadIdx.x;   // 0 .. 512*256-1 (float4 units)
    const int r = i >> 8;
    const int c = (i & 255) * 4;
    float4 v = *reinterpret_cast<const float4*>(&w[(long)r * F3 + DIM + c]);
    v.x = __uint_as_float(f2tf32(v.x));
    v.y = __uint_as_float(f2tf32(v.y));
    v.z = __uint_as_float(f2tf32(v.z));
    v.w = __uint_as_float(f2tf32(v.w));
    *reinterpret_cast<float4*>(&g_wkv[(long)r * FKV + c]) = v;
}

// ======================= transpose (wqT for GEMM2) ========================
__global__ __launch_bounds__(256) void transpose_k(
    const float* __restrict__ in, float* __restrict__ out,
    int R, int C, int ldin)
{
    __shared__ float t[32][33];
    const int c0 = blockIdx.x * 32;
    const int r0 = blockIdx.y * 32;
    const int tx = threadIdx.x & 31;
    const int ty = threadIdx.x >> 5;
#pragma unroll
    for (int i = 0; i < 4; i++)
        t[ty + i * 8][tx] = in[(long)(r0 + ty + i * 8) * ldin + c0 + tx];
    __syncthreads();
#pragma unroll
    for (int i = 0; i < 4; i++)
        out[(long)(c0 + ty + i * 8) * R + r0 + tx] = t[tx][ty + i * 8];
}

// ======================= big GEMM: cp.async 4-stage, 128x256 ===============
// C[m,n] = sum_k A[k,m]*B[k,n] (+bias[m]). Inputs MUST be pre-rounded tf32.
// 256 threads = 8 warps (2m x 4n), warp tile 64x64 (4x8 m16n8k8 tiles).
#define GA_BM 128
#define GA_BN 256
#define GA_BK 16
#define GA_AW 136              // A row stride in words (128 + 8 pad)
#define GA_BW 264              // B row stride in words (256 + 8 pad)
#define GA_AOFF(s) ((s) * (GA_BK * GA_AW))
#define GA_BOFF(s) (4 * GA_BK * GA_AW + (s) * (GA_BK * GA_BW))
#define GA_SMEM ((4 * GA_BK * GA_AW + 4 * GA_BK * GA_BW) * 4)   // 102400 B

__global__ __launch_bounds__(256, 1) void gemm_async(
    const float* __restrict__ A, const float* __restrict__ B,
    float* __restrict__ C,
    int lda, int ldb, int ldc, int K,
    long sA, long sB, long sC,
    const float* __restrict__ bias)
{
    extern __shared__ uint32_t sm[];
    const uint32_t sb = smem_u32(sm);

    A += (long)blockIdx.z * sA;
    B += (long)blockIdx.z * sB;
    C += (long)blockIdx.z * sC;

    const int m0 = blockIdx.y * GA_BM;
    const int n0 = blockIdx.x * GA_BN;

    const int tid  = threadIdx.x;
    const int lane = tid & 31;
    const int g    = lane >> 2;
    const int tg   = lane & 3;
    const int warp = tid >> 5;
    const int wm   = (warp >> 2) * 64;
    const int wn   = (warp & 3) * 64;

    const int NKT = K / GA_BK;

    auto stage = [&](int kt, int s) {
        const int k0 = kt * GA_BK;
#pragma unroll
        for (int i = 0; i < 2; i++) {            // A: 512 16B units
            const int u = tid + 256 * i;
            const int row = u >> 5, c4 = (u & 31) * 4;
            cp16(sb + (GA_AOFF(s) + row * GA_AW + c4) * 4,
                 A + (long)(k0 + row) * lda + m0 + c4);
        }
#pragma unroll
        for (int j = 0; j < 4; j++) {            // B: 1024 16B units
            const int u = tid + 256 * j;
            const int row = u >> 6, c4 = (u & 63) * 4;
            cp16(sb + (GA_BOFF(s) + row * GA_BW + c4) * 4,
                 B + (long)(k0 + row) * ldb + n0 + c4);
        }
    };

    float acc[4][8][4];
#pragma unroll
    for (int i = 0; i < 4; i++)
#pragma unroll
        for (int j = 0; j < 8; j++)
#pragma unroll
            for (int q = 0; q < 4; q++) acc[i][j][q] = 0.0f;

    // prologue: 3 stages in flight
    stage(0, 0); asm volatile("cp.async.commit_group;" ::: "memory");
    stage(1, 1); asm volatile("cp.async.commit_group;" ::: "memory");
    stage(2, 2); asm volatile("cp.async.commit_group;" ::: "memory");

    for (int kt = 0; kt < NKT; kt++) {
        asm volatile("cp.async.wait_group 2;" ::: "memory");
        __syncthreads();

        if (kt + 3 < NKT) stage(kt + 3, (kt + 3) & 3);
        asm volatile("cp.async.commit_group;" ::: "memory");

        const uint32_t* SA = sm + GA_AOFF(kt & 3);
        const uint32_t* SB = sm + GA_BOFF(kt & 3);

#pragma unroll
        for (int ks = 0; ks < GA_BK; ks += 8) {
            uint32_t af[4][4];
            uint32_t bf[8][2];
#pragma unroll
            for (int mt = 0; mt < 4; mt++) {
                const int mb = wm + mt * 16;
                af[mt][0] = SA[(ks + tg    ) * GA_AW + mb + g];
                af[mt][1] = SA[(ks + tg    ) * GA_AW + mb + g + 8];
                af[mt][2] = SA[(ks + tg + 4) * GA_AW + mb + g];
                af[mt][3] = SA[(ks + tg + 4) * GA_AW + mb + g + 8];
            }
#pragma unroll
            for (int nt = 0; nt < 8; nt++) {
                const int nb = wn + nt * 8;
                bf[nt][0] = SB[(ks + tg    ) * GA_BW + nb + g];
                bf[nt][1] = SB[(ks + tg + 4) * GA_BW + nb + g];
            }
#pragma unroll
            for (int mt = 0; mt < 4; mt++)
#pragma unroll
                for (int nt = 0; nt < 8; nt++)
                    mma_tf32(acc[mt][nt], af[mt], bf[nt]);
        }
        __syncthreads();
    }

#pragma unroll
    for (int mt = 0; mt < 4; mt++) {
        const int m = m0 + wm + mt * 16 + g;
        const float bv0 = bias ? bias[m]     : 0.0f;
        const float bv8 = bias ? bias[m + 8] : 0.0f;
#pragma unroll
        for (int nt = 0; nt < 8; nt++) {
            const int n = n0 + wn + nt * 8 + 2 * tg;
            float2 o0 = {acc[mt][nt][0] + bv0, acc[mt][nt][1] + bv0};
            float2 o1 = {acc[mt][nt][2] + bv8, acc[mt][nt][3] + bv8};
            *reinterpret_cast<float2*>(&C[(long)m * ldc + n])       = o0;
            *reinterpret_cast<float2*>(&C[(long)(m + 8) * ldc + n]) = o1;
        }
    }
}

// ======================= small GEMM (cvt staging) for M2 ===================
#define BM 128
#define BN 128
#define BK 16

__global__ __launch_bounds__(256, 2) void gemm_tf32(
    const float* __restrict__ A, const float* __restrict__ B,
    float* __restrict__ C,
    int lda, int ldb, int ldc, int K,
    long sA, long sB, long sC,
    const float* __restrict__ bias, int round_out)
{
    A += (long)blockIdx.z * sA;
    B += (long)blockIdx.z * sB;
    C += (long)blockIdx.z * sC;

    const int m0 = blockIdx.y * BM;
    const int n0 = blockIdx.x * BN;

    __shared__ uint32_t As[2][BK][BM + 4];
    __shared__ uint32_t Bs[2][BK][BN + 4];

    const int tid  = threadIdx.x;
    const int lane = tid & 31;
    const int g    = lane >> 2;
    const int tg   = lane & 3;
    const int warp = tid >> 5;
    const int wm   = (warp >> 2) * 64;
    const int wn   = (warp & 3) * 32;

    const int srow0 = tid >> 5;
    const int scol0 = (tid & 31) * 4;
    const int srow1 = 8 + (tid >> 5);
    const int scol1 = scol0;

    float c[4][4][4];
#pragma unroll
    for (int i = 0; i < 4; i++)
#pragma unroll
        for (int j = 0; j < 4; j++)
#pragma unroll
            for (int q = 0; q < 4; q++) c[i][j][q] = 0.0f;

    const int ntiles = K / BK;
    float4 pa0, pa1, pb0, pb1;

    pa0 = *reinterpret_cast<const float4*>(&A[(long)srow0 * lda + m0 + scol0]);
    pa1 = *reinterpret_cast<const float4*>(&A[(long)srow1 * lda + m0 + scol1]);
    pb0 = *reinterpret_cast<const float4*>(&B[(long)srow0 * ldb + n0 + scol0]);
    pb1 = *reinterpret_cast<const float4*>(&B[(long)srow1 * ldb + n0 + scol1]);

    int buf = 0;
    {
        uint4 ua0 = {f2tf32(pa0.x), f2tf32(pa0.y), f2tf32(pa0.z), f2tf32(pa0.w)};
        uint4 ua1 = {f2tf32(pa1.x), f2tf32(pa1.y), f2tf32(pa1.z), f2tf32(pa1.w)};
        uint4 ub0 = {f2tf32(pb0.x), f2tf32(pb0.y), f2tf32(pb0.z), f2tf32(pb0.w)};
        uint4 ub1 = {f2tf32(pb1.x), f2tf32(pb1.y), f2tf32(pb1.z), f2tf32(pb1.w)};
        *reinterpret_cast<uint4*>(&As[0][srow0][scol0]) = ua0;
        *reinterpret_cast<uint4*>(&As[0][srow1][scol1]) = ua1;
        *reinterpret_cast<uint4*>(&Bs[0][srow0][scol0]) = ub0;
        *reinterpret_cast<uint4*>(&Bs[0][srow1][scol1]) = ub1;
    }
    __syncthreads();

    for (int kt = 0; kt < ntiles; kt++) {
        const bool has_next = (kt + 1) < ntiles;
        if (has_next) {
            const long kb = (long)(kt + 1) * BK;
            pa0 = *reinterpret_cast<const float4*>(&A[(kb + srow0) * lda + m0 + scol0]);
            pa1 = *reinterpret_cast<const float4*>(&A[(kb + srow1) * lda + m0 + scol1]);
            pb0 = *reinterpret_cast<const float4*>(&B[(kb + srow0) * ldb + n0 + scol0]);
            pb1 = *reinterpret_cast<const float4*>(&B[(kb + srow1) * ldb + n0 + scol1]);
        }

#pragma unroll
        for (int ks = 0; ks < BK; ks += 8) {
            uint32_t af[4][4];
            uint32_t bf[4][2];
#pragma unroll
            for (int mt = 0; mt < 4; mt++) {
                const int mb = wm + mt * 16;
                af[mt][0] = As[buf][ks + tg    ][mb + g];
                af[mt][1] = As[buf][ks + tg    ][mb + g + 8];
                af[mt][2] = As[buf][ks + tg + 4][mb + g];
                af[mt][3] = As[buf][ks + tg + 4][mb + g + 8];
            }
#pragma unroll
            for (int nt = 0; nt < 4; nt++) {
                const int nb = wn + nt * 8;
                bf[nt][0] = Bs[buf][ks + tg    ][nb + g];
                bf[nt][1] = Bs[buf][ks + tg + 4][nb + g];
            }
#pragma unroll
            for (int mt = 0; mt < 4; mt++)
#pragma unroll
                for (int nt = 0; nt < 4; nt++)
                    mma_tf32(c[mt][nt], af[mt], bf[nt]);
        }

        if (has_next) {
            uint4 ua0 = {f2tf32(pa0.x), f2tf32(pa0.y), f2tf32(pa0.z), f2tf32(pa0.w)};
            uint4 ua1 = {f2tf32(pa1.x), f2tf32(pa1.y), f2tf32(pa1.z), f2tf32(pa1.w)};
            uint4 ub0 = {f2tf32(pb0.x), f2tf32(pb0.y), f2tf32(pb0.z), f2tf32(pb0.w)};
            uint4 ub1 = {f2tf32(pb1.x), f2tf32(pb1.y), f2tf32(pb1.z), f2tf32(pb1.w)};
            const int nb = buf ^ 1;
            *reinterpret_cast<uint4*>(&As[nb][srow0][scol0]) = ua0;
            *reinterpret_cast<uint4*>(&As[nb][srow1][scol1]) = ua1;
            *reinterpret_cast<uint4*>(&Bs[nb][srow0][scol0]) = ub0;
            *reinterpret_cast<uint4*>(&Bs[nb][srow1][scol1]) = ub1;
        }
        __syncthreads();
        buf ^= 1;
    }

#pragma unroll
    for (int mt = 0; mt < 4; mt++) {
        const int m = m0 + wm + mt * 16 + g;
        const float bv0 = bias ? bias[m]     : 0.0f;
        const float bv8 = bias ? bias[m + 8] : 0.0f;
#pragma unroll
        for (int nt = 0; nt < 4; nt++) {
            const int n = n0 + wn + nt * 8 + 2 * tg;
            float2 o0 = {c[mt][nt][0] + bv0, c[mt][nt][1] + bv0};
            float2 o1 = {c[mt][nt][2] + bv8, c[mt][nt][3] + bv8};
            if (round_out) {
                o0.x = __uint_as_float(f2tf32(o0.x));
                o0.y = __uint_as_float(f2tf32(o0.y));
                o1.x = __uint_as_float(f2tf32(o1.x));
                o1.y = __uint_as_float(f2tf32(o1.y));
            }
            *reinterpret_cast<float2*>(&C[(long)m * ldc + n])       = o0;
            *reinterpret_cast<float2*>(&C[(long)(m + 8) * ldc + n]) = o1;
        }
    }
}

// ======================= softmax stats (no write-back) =====================
__global__ __launch_bounds__(256) void softmax_stats()
{
    const int row = blockIdx.x;           // 0 .. BATCH*DIM-1
    const int b = row / DIM;
    const int r = row % DIM;
    const float* p = g_qkv + (long)b * FKV * LSEQ + (long)r * LSEQ;

    const int tid = threadIdx.x;
    float4 v[4];
    float mx = -1e30f;
#pragma unroll
    for (int i = 0; i < 4; i++) {
        v[i] = reinterpret_cast<const float4*>(p)[tid + i * 256];
        mx = fmaxf(mx, fmaxf(fmaxf(v[i].x, v[i].y), fmaxf(v[i].z, v[i].w)));
    }

    __shared__ float red[8];
#pragma unroll
    for (int o = 16; o; o >>= 1) mx = fmaxf(mx, __shfl_xor_sync(~0u, mx, o));
    if ((tid & 31) == 0) red[tid >> 5] = mx;
    __syncthreads();
    mx = red[0];
#pragma unroll
    for (int i = 1; i < 8; i++) mx = fmaxf(mx, red[i]);
    __syncthreads();

    float s = 0.0f;
#pragma unroll
    for (int i = 0; i < 4; i++) {
        s += expf(v[i].x - mx) + expf(v[i].y - mx)
           + expf(v[i].z - mx) + expf(v[i].w - mx);
    }
#pragma unroll
    for (int o = 16; o; o >>= 1) s += __shfl_xor_sync(~0u, s, o);
    if ((tid & 31) == 0) red[tid >> 5] = s;
    __syncthreads();
    if (tid == 0) {
        s = red[0];
#pragma unroll
        for (int i = 1; i < 8; i++) s += red[i];
        g_stats[row] = make_float2(mx, 1.0f / s);
    }
}

// ======================= ctx partials: tensor cores + fused softmax ========
#define CP 72
__global__ __launch_bounds__(256) void ctx_partial_tc()
{
    const int bh = blockIdx.x;
    const int split = blockIdx.y;
    const int b = bh >> 3, h = bh & 7;
    const float* Kp = g_qkv + (long)b * FKV * LSEQ + (long)(h * DH) * LSEQ;
    const float* Vp = g_qkv + (long)b * FKV * LSEQ + (long)(DIM + h * DH) * LSEQ;
    const int n0 = split * (LSEQ / NSPLIT);

    __shared__ uint32_t Ks[32][CP];
    __shared__ uint32_t Vs[32][CP];

    const int tid  = threadIdx.x;
    const int lane = tid & 31;
    const int g    = lane >> 2;
    const int tg   = lane & 3;
    const int warp = tid >> 5;
    const int wm   = (warp >> 2) * 32;
    const int wn   = (warp & 3) * 16;

    const int r = tid >> 2;
    const int q = tid & 3;
    const float m_r = g_stats[b * DIM + h * DH + r].x;

    float acc[2][2][4];
#pragma unroll
    for (int i = 0; i < 2; i++)
#pragma unroll
        for (int j = 0; j < 2; j++)
#pragma unroll
            for (int p = 0; p < 4; p++) acc[i][j][p] = 0.0f;

    float4 k0, k1, v0, v1;
    const float* kr = Kp + (long)r * LSEQ + n0 + q * 8;
    const float* vr = Vp + (long)r * LSEQ + n0 + q * 8;
    k0 = *reinterpret_cast<const float4*>(kr);
    k1 = *reinterpret_cast<const float4*>(kr + 4);
    v0 = *reinterpret_cast<const float4*>(vr);
    v1 = *reinterpret_cast<const float4*>(vr + 4);

    for (int c = 0; c < 8; c++) {
        const int nb = q * 8;
        Ks[nb    ][r] = f2tf32(expf(k0.x - m_r));
        Ks[nb + 1][r] = f2tf32(expf(k0.y - m_r));
        Ks[nb + 2][r] = f2tf32(expf(k0.z - m_r));
        Ks[nb + 3][r] = f2tf32(expf(k0.w - m_r));
        Ks[nb + 4][r] = f2tf32(expf(k1.x - m_r));
        Ks[nb + 5][r] = f2tf32(expf(k1.y - m_r));
        Ks[nb + 6][r] = f2tf32(expf(k1.z - m_r));
        Ks[nb + 7][r] = f2tf32(expf(k1.w - m_r));
        Vs[nb    ][r] = f2tf32(v0.x);
        Vs[nb + 1][r] = f2tf32(v0.y);
        Vs[nb + 2][r] = f2tf32(v0.z);
        Vs[nb + 3][r] = f2tf32(v0.w);
        Vs[nb + 4][r] = f2tf32(v1.x);
        Vs[nb + 5][r] = f2tf32(v1.y);
        Vs[nb + 6][r] = f2tf32(v1.z);
        Vs[nb + 7][r] = f2tf32(v1.w);
        __syncthreads();

        if (c + 1 < 8) {
            const float* krn = kr + (c + 1) * 32;
            const float* vrn = vr + (c + 1) * 32;
            k0 = *reinterpret_cast<const float4*>(krn);
            k1 = *reinterpret_cast<const float4*>(krn + 4);
            v0 = *reinterpret_cast<const float4*>(vrn);
            v1 = *reinterpret_cast<const float4*>(vrn + 4);
        }

#pragma unroll
        for (int ks = 0; ks < 32; ks += 8) {
            uint32_t af[2][4];
            uint32_t bf[2][2];
#pragma unroll
            for (int mt = 0; mt < 2; mt++) {
                const int mb = wm + mt * 16;
                af[mt][0] = Ks[ks + tg    ][mb + g];
                af[mt][1] = Ks[ks + tg    ][mb + g + 8];
                af[mt][2] = Ks[ks + tg + 4][mb + g];
                af[mt][3] = Ks[ks + tg + 4][mb + g + 8];
            }
#pragma unroll
            for (int nt = 0; nt < 2; nt++) {
                const int nbx = wn + nt * 8;
                bf[nt][0] = Vs[ks + tg    ][nbx + g];
                bf[nt][1] = Vs[ks + tg + 4][nbx + g];
            }
#pragma unroll
            for (int mt = 0; mt < 2; mt++)
#pragma unroll
                for (int nt = 0; nt < 2; nt++)
                    mma_tf32(acc[mt][nt], af[mt], bf[nt]);
        }
        __syncthreads();
    }

    float* cp = g_ctxp + ((long)bh * NSPLIT + split) * DH * DH;
#pragma unroll
    for (int mt = 0; mt < 2; mt++) {
        const int m = wm + mt * 16 + g;
        const float is0 = g_stats[b * DIM + h * DH + m].y;
        const float is8 = g_stats[b * DIM + h * DH + m + 8].y;
#pragma unroll
        for (int nt = 0; nt < 2; nt++) {
            const int n = wn + nt * 8 + 2 * tg;
            float2 o0 = {acc[mt][nt][0] * is0, acc[mt][nt][1] * is0};
            float2 o1 = {acc[mt][nt][2] * is8, acc[mt][nt][3] * is8};
            *reinterpret_cast<float2*>(&cp[(long)m * DH + n])       = o0;
            *reinterpret_cast<float2*>(&cp[(long)(m + 8) * DH + n]) = o1;
        }
    }
}

// ======================= parallel split reduce =============================
__global__ __launch_bounds__(256) void ctx_reduce()
{
    const int idx = blockIdx.x * 256 + threadIdx.x;
    const int bh = idx >> 12;
    const int i  = idx & 4095;
    float s = 0.0f;
#pragma unroll
    for (int sp = 0; sp < NSPLIT; sp++)
        s += g_ctxp[((long)bh * NSPLIT + sp) * DH * DH + i];
    g_ctx[(long)bh * DH * DH + i] = s;
}

// ======================= fold w_out into ctx ===============================
__global__ __launch_bounds__(256) void wctx_fold(const float* __restrict__ w_out)
{
    const int bh = blockIdx.x;
    const int b = bh / HEADS, h = bh % HEADS;
    __shared__ float cs[64][65];
    const int tid = threadIdx.x;

    const float* cp = g_ctx + (long)bh * DH * DH;
    for (int i = tid; i < DH * DH; i += 256) cs[i >> 6][i & 63] = cp[i];
    __syncthreads();

    float* outp = g_wctxT + (long)b * DIM * DIM + (long)(h * DH) * DIM;

    for (int cb = 0; cb < 2; cb++) {
        const int c = cb * 256 + tid;
        float w[64];
#pragma unroll
        for (int e = 0; e < 64; e++) w[e] = w_out[(h * DH + e) * DIM + c];
#pragma unroll 4
        for (int d = 0; d < 64; d++) {
            float s = 0.0f;
#pragma unroll
            for (int e = 0; e < 64; e++) s = fmaf(cs[d][e], w[e], s);
            outp[(long)d * DIM + c] = s * SCALE;
        }
    }
}

// ---------------------------------------------------------------------------
extern "C" void kernel_launch(void* const* d_in, const int* in_sizes, int n_in,
                              void* d_out, int out_size)
{
    const float* x      = (const float*)d_in[0];   // (B, 512, 4096)
    const float* w_qkv  = (const float*)d_in[1];   // (512, 1536)
    const float* w_out  = (const float*)d_in[2];   // (512, 512)
    const float* b_out  = (const float*)d_in[3];   // (512,)
    float* out = (float*)d_out;                    // (B, 512, 4096)

    float* qkv;
    float* xr;
    float* wkv;
    float* wctxT;
    float* wqT;
    float* M2;
    cudaGetSymbolAddress((void**)&qkv,   g_qkv);
    cudaGetSymbolAddress((void**)&xr,    g_xr);
    cudaGetSymbolAddress((void**)&wkv,   g_wkv);
    cudaGetSymbolAddress((void**)&wctxT, g_wctxT);
    cudaGetSymbolAddress((void**)&wqT,   g_wqT);
    cudaGetSymbolAddress((void**)&M2,    g_M2);

    cudaFuncSetAttribute(gemm_async, cudaFuncAttributeMaxDynamicSharedMemorySize, GA_SMEM);

    // 0) pre-round inputs (RNA tf32): x -> xr, w_kv slice -> wkv; wqT raw
    {
        const int n4 = BATCH * DIM * LSEQ / 4;
        rna_vec<<<(n4 + 255) / 256, 256>>>((const float4*)x, (float4*)xr, n4);
        rna_wkv<<<(DIM * FKV / 4) / 256, 256>>>(w_qkv);
        dim3 g(DIM / 32, DIM / 32, 1);
        transpose_k<<<g, 256>>>(w_qkv, wqT, DIM, DIM, F3);
    }

    // 1) k,v = W_kv^T @ x per batch  (async GEMM, pre-rounded operands)
    {
        dim3 grid(LSEQ / GA_BN, FKV / GA_BM, BATCH);
        gemm_async<<<grid, 256, GA_SMEM>>>(wkv, xr, qkv,
                                           FKV, LSEQ, LSEQ, DIM,
                                           0L, (long)DIM * LSEQ, (long)FKV * LSEQ,
                                           nullptr);
    }

    // 2) softmax stats per k row
    softmax_stats<<<BATCH * DIM, 256>>>();

    // 3) ctx partials via tensor cores with fused exp/normalize
    {
        dim3 grid(BATCH * HEADS, NSPLIT);
        ctx_partial_tc<<<grid, 256>>>();
    }

    // 3b) parallel reduce
    ctx_reduce<<<(BATCH * HEADS * DH * DH) / 256, 256>>>();

    // 4) fold w_out into ctx (includes SCALE)
    wctx_fold<<<BATCH * HEADS, 256>>>(w_out);

    // 5) M2 = wqT^T-fold (small; rounds output for the async GEMM)
    {
        dim3 grid(DIM / BN, DIM / BM, BATCH);
        gemm_tf32<<<grid, 256>>>(wqT, wctxT, M2,
                                 DIM, DIM, DIM, DIM,
                                 0L, (long)DIM * DIM, (long)DIM * DIM,
                                 nullptr, 1);
    }

    // 6) out = M2^T @ x + bias  (async GEMM, pre-rounded operands)
    {
        dim3 grid(LSEQ / GA_BN, DIM / GA_BM, BATCH);
        gemm_async<<<grid, 256, GA_SMEM>>>(M2, xr, out,
                                           DIM, LSEQ, LSEQ, DIM,
                                           (long)DIM * DIM, (long)DIM * LSEQ, (long)DIM * LSEQ,
                                           b_out);
    }
}

// round 11
// speedup vs baseline: 1.7603x; 1.0076x over previous
#include <cuda_runtime.h>
#include <math.h>
#include <stdint.h>

#define BATCH 8
#define DIM   512
#define HEADS 8
#define DH    64
#define LSEQ  4096
#define F3    1536            // 3 * HEADS * DIM_HEAD
#define FKV   1024            // k,v thirds only
#define SCALE 0.125f          // DH^-0.5
#define NSPLIT 16

// ---------------- scratch (device globals; no allocation allowed) ----------
__device__ float  g_qkv[(size_t)BATCH * FKV * LSEQ];                 // 134 MB (k,v raw)
__device__ float  g_xr[(size_t)BATCH * DIM * LSEQ];                  // 67 MB (x, RNA-rounded)
__device__ float  g_wkv[(size_t)DIM * FKV];                          // 2 MB (w kv slice, RNA)
__device__ float  g_ctxp[(size_t)BATCH * HEADS * NSPLIT * DH * DH];  // 16.8 MB
__device__ float  g_ctx[(size_t)BATCH * HEADS * DH * DH];            // 1 MB
__device__ float2 g_stats[(size_t)BATCH * DIM];                      // (max, 1/sumexp)
__device__ float  g_wctxT[(size_t)BATCH * DIM * DIM];                // 8 MB
__device__ float  g_wqT[(size_t)DIM * DIM];                          // 1 MB
__device__ float  g_M2[(size_t)BATCH * DIM * DIM];                   // 8 MB (RNA-rounded)

// ======================= helpers ==========================================
__device__ __forceinline__ uint32_t f2tf32(float x) {
    uint32_t u;
    asm("cvt.rna.tf32.f32 %0, %1;" : "=r"(u) : "f"(x));
    return u;
}

__device__ __forceinline__ void mma_tf32(float c[4], const uint32_t a[4], const uint32_t b[2]) {
    asm volatile(
        "mma.sync.aligned.m16n8k8.row.col.f32.tf32.tf32.f32 "
        "{%0,%1,%2,%3}, {%4,%5,%6,%7}, {%8,%9}, {%0,%1,%2,%3};"
        : "+f"(c[0]), "+f"(c[1]), "+f"(c[2]), "+f"(c[3])
        : "r"(a[0]), "r"(a[1]), "r"(a[2]), "r"(a[3]), "r"(b[0]), "r"(b[1]));
}

__device__ __forceinline__ uint32_t smem_u32(const void* p) {
    uint32_t a;
    asm("{ .reg .u64 t; cvta.to.shared.u64 t, %1; cvt.u32.u64 %0, t; }" : "=r"(a) : "l"(p));
    return a;
}
__device__ __forceinline__ void cp16(uint32_t dst, const void* src) {
    asm volatile("cp.async.cg.shared.global [%0], [%1], 16;" :: "r"(dst), "l"(src));
}

// ======================= RNA pre-rounding passes ===========================
__global__ __launch_bounds__(256) void rna_vec(const float4* __restrict__ in,
                                               float4* __restrict__ out, int n4)
{
    const int i = blockIdx.x * 256 + threadIdx.x;
    if (i < n4) {
        float4 v = in[i];
        v.x = __uint_as_float(f2tf32(v.x));
        v.y = __uint_as_float(f2tf32(v.y));
        v.z = __uint_as_float(f2tf32(v.z));
        v.w = __uint_as_float(f2tf32(v.w));
        out[i] = v;
    }
}

// copy+round w_qkv columns [512,1536) into contiguous (512 x 1024)
__global__ __launch_bounds__(256) void rna_wkv(const float* __restrict__ w)
{
    const int i = blockIdx.x * 256 + threadIdx.x;   // float4 units
    const int r = i >> 8;
    const int c = (i & 255) * 4;
    float4 v = *reinterpret_cast<const float4*>(&w[(long)r * F3 + DIM + c]);
    v.x = __uint_as_float(f2tf32(v.x));
    v.y = __uint_as_float(f2tf32(v.y));
    v.z = __uint_as_float(f2tf32(v.z));
    v.w = __uint_as_float(f2tf32(v.w));
    *reinterpret_cast<float4*>(&g_wkv[(long)r * FKV + c]) = v;
}

// ======================= transpose (wqT for GEMM2) ========================
__global__ __launch_bounds__(256) void transpose_k(
    const float* __restrict__ in, float* __restrict__ out,
    int R, int C, int ldin)
{
    __shared__ float t[32][33];
    const int c0 = blockIdx.x * 32;
    const int r0 = blockIdx.y * 32;
    const int tx = threadIdx.x & 31;
    const int ty = threadIdx.x >> 5;
#pragma unroll
    for (int i = 0; i < 4; i++)
        t[ty + i * 8][tx] = in[(long)(r0 + ty + i * 8) * ldin + c0 + tx];
    __syncthreads();
#pragma unroll
    for (int i = 0; i < 4; i++)
        out[(long)(c0 + ty + i * 8) * R + r0 + tx] = t[tx][ty + i * 8];
}

// ======================= big GEMM: cp.async 4-stage, 128x256 ===============
// C[m,n] = sum_k A[k,m]*B[k,n] (+bias[m]). Inputs MUST be pre-rounded tf32.
// 256 threads = 8 warps (2m x 4n), warp tile 64x64 (4x8 m16n8k8 tiles).
// Whole-slab fragment batch load -> back-to-back MMA train (latency hiding).
#define GA_BM 128
#define GA_BN 256
#define GA_BK 16
#define GA_AW 136              // A row stride in words (128 + 8 pad)
#define GA_BW 264              // B row stride in words (256 + 8 pad)
#define GA_AOFF(s) ((s) * (GA_BK * GA_AW))
#define GA_BOFF(s) (4 * GA_BK * GA_AW + (s) * (GA_BK * GA_BW))
#define GA_SMEM ((4 * GA_BK * GA_AW + 4 * GA_BK * GA_BW) * 4)   // 102400 B

__global__ __launch_bounds__(256, 1) void gemm_async(
    const float* __restrict__ A, const float* __restrict__ B,
    float* __restrict__ C,
    int lda, int ldb, int ldc, int K,
    long sA, long sB, long sC,
    const float* __restrict__ bias)
{
    extern __shared__ uint32_t sm[];
    const uint32_t sb = smem_u32(sm);

    A += (long)blockIdx.z * sA;
    B += (long)blockIdx.z * sB;
    C += (long)blockIdx.z * sC;

    const int m0 = blockIdx.y * GA_BM;
    const int n0 = blockIdx.x * GA_BN;

    const int tid  = threadIdx.x;
    const int lane = tid & 31;
    const int g    = lane >> 2;
    const int tg   = lane & 3;
    const int warp = tid >> 5;
    const int wm   = (warp >> 2) * 64;
    const int wn   = (warp & 3) * 64;

    const int NKT = K / GA_BK;

    auto stage = [&](int kt, int s) {
        const int k0 = kt * GA_BK;
#pragma unroll
        for (int i = 0; i < 2; i++) {            // A: 512 16B units
            const int u = tid + 256 * i;
            const int row = u >> 5, c4 = (u & 31) * 4;
            cp16(sb + (GA_AOFF(s) + row * GA_AW + c4) * 4,
                 A + (long)(k0 + row) * lda + m0 + c4);
        }
#pragma unroll
        for (int j = 0; j < 4; j++) {            // B: 1024 16B units
            const int u = tid + 256 * j;
            const int row = u >> 6, c4 = (u & 63) * 4;
            cp16(sb + (GA_BOFF(s) + row * GA_BW + c4) * 4,
                 B + (long)(k0 + row) * ldb + n0 + c4);
        }
    };

    float acc[4][8][4];
#pragma unroll
    for (int i = 0; i < 4; i++)
#pragma unroll
        for (int j = 0; j < 8; j++)
#pragma unroll
            for (int q = 0; q < 4; q++) acc[i][j][q] = 0.0f;

    // prologue: 3 stages in flight
    stage(0, 0); asm volatile("cp.async.commit_group;" ::: "memory");
    stage(1, 1); asm volatile("cp.async.commit_group;" ::: "memory");
    stage(2, 2); asm volatile("cp.async.commit_group;" ::: "memory");

    for (int kt = 0; kt < NKT; kt++) {
        asm volatile("cp.async.wait_group 2;" ::: "memory");
        __syncthreads();
        // NOTE: this sync also orders all warps' (kt-1) MMAs before the
        // stage() below overwrites buffer (kt-1)&3 — no tail sync needed.

        if (kt + 3 < NKT) stage(kt + 3, (kt + 3) & 3);
        asm volatile("cp.async.commit_group;" ::: "memory");

        const uint32_t* SA = sm + GA_AOFF(kt & 3);
        const uint32_t* SB = sm + GA_BOFF(kt & 3);

        // batch-load ALL fragments for the BK=16 slab (2 ks-blocks), then
        // run the 64-MMA train — LDS latency amortizes over the whole train.
        uint32_t af[2][4][4];
        uint32_t bf[2][8][2];
#pragma unroll
        for (int s = 0; s < 2; s++) {
            const int ks = s * 8;
#pragma unroll
            for (int mt = 0; mt < 4; mt++) {
                const int mb = wm + mt * 16;
                af[s][mt][0] = SA[(ks + tg    ) * GA_AW + mb + g];
                af[s][mt][1] = SA[(ks + tg    ) * GA_AW + mb + g + 8];
                af[s][mt][2] = SA[(ks + tg + 4) * GA_AW + mb + g];
                af[s][mt][3] = SA[(ks + tg + 4) * GA_AW + mb + g + 8];
            }
#pragma unroll
            for (int nt = 0; nt < 8; nt++) {
                const int nb = wn + nt * 8;
                bf[s][nt][0] = SB[(ks + tg    ) * GA_BW + nb + g];
                bf[s][nt][1] = SB[(ks + tg + 4) * GA_BW + nb + g];
            }
        }
#pragma unroll
        for (int s = 0; s < 2; s++)
#pragma unroll
            for (int mt = 0; mt < 4; mt++)
#pragma unroll
                for (int nt = 0; nt < 8; nt++)
                    mma_tf32(acc[mt][nt], af[s][mt], bf[s][nt]);
    }

#pragma unroll
    for (int mt = 0; mt < 4; mt++) {
        const int m = m0 + wm + mt * 16 + g;
        const float bv0 = bias ? bias[m]     : 0.0f;
        const float bv8 = bias ? bias[m + 8] : 0.0f;
#pragma unroll
        for (int nt = 0; nt < 8; nt++) {
            const int n = n0 + wn + nt * 8 + 2 * tg;
            float2 o0 = {acc[mt][nt][0] + bv0, acc[mt][nt][1] + bv0};
            float2 o1 = {acc[mt][nt][2] + bv8, acc[mt][nt][3] + bv8};
            *reinterpret_cast<float2*>(&C[(long)m * ldc + n])       = o0;
            *reinterpret_cast<float2*>(&C[(long)(m + 8) * ldc + n]) = o1;
        }
    }
}

// ======================= small GEMM (cvt staging) for M2 ===================
#define BM 128
#define BN 128
#define BK 16

__global__ __launch_bounds__(256, 2) void gemm_tf32(
    const float* __restrict__ A, const float* __restrict__ B,
    float* __restrict__ C,
    int lda, int ldb, int ldc, int K,
    long sA, long sB, long sC,
    const float* __restrict__ bias, int round_out)
{
    A += (long)blockIdx.z * sA;
    B += (long)blockIdx.z * sB;
    C += (long)blockIdx.z * sC;

    const int m0 = blockIdx.y * BM;
    const int n0 = blockIdx.x * BN;

    __shared__ uint32_t As[2][BK][BM + 4];
    __shared__ uint32_t Bs[2][BK][BN + 4];

    const int tid  = threadIdx.x;
    const int lane = tid & 31;
    const int g    = lane >> 2;
    const int tg   = lane & 3;
    const int warp = tid >> 5;
    const int wm   = (warp >> 2) * 64;
    const int wn   = (warp & 3) * 32;

    const int srow0 = tid >> 5;
    const int scol0 = (tid & 31) * 4;
    const int srow1 = 8 + (tid >> 5);
    const int scol1 = scol0;

    float c[4][4][4];
#pragma unroll
    for (int i = 0; i < 4; i++)
#pragma unroll
        for (int j = 0; j < 4; j++)
#pragma unroll
            for (int q = 0; q < 4; q++) c[i][j][q] = 0.0f;

    const int ntiles = K / BK;
    float4 pa0, pa1, pb0, pb1;

    pa0 = *reinterpret_cast<const float4*>(&A[(long)srow0 * lda + m0 + scol0]);
    pa1 = *reinterpret_cast<const float4*>(&A[(long)srow1 * lda + m0 + scol1]);
    pb0 = *reinterpret_cast<const float4*>(&B[(long)srow0 * ldb + n0 + scol0]);
    pb1 = *reinterpret_cast<const float4*>(&B[(long)srow1 * ldb + n0 + scol1]);

    int buf = 0;
    {
        uint4 ua0 = {f2tf32(pa0.x), f2tf32(pa0.y), f2tf32(pa0.z), f2tf32(pa0.w)};
        uint4 ua1 = {f2tf32(pa1.x), f2tf32(pa1.y), f2tf32(pa1.z), f2tf32(pa1.w)};
        uint4 ub0 = {f2tf32(pb0.x), f2tf32(pb0.y), f2tf32(pb0.z), f2tf32(pb0.w)};
        uint4 ub1 = {f2tf32(pb1.x), f2tf32(pb1.y), f2tf32(pb1.z), f2tf32(pb1.w)};
        *reinterpret_cast<uint4*>(&As[0][srow0][scol0]) = ua0;
        *reinterpret_cast<uint4*>(&As[0][srow1][scol1]) = ua1;
        *reinterpret_cast<uint4*>(&Bs[0][srow0][scol0]) = ub0;
        *reinterpret_cast<uint4*>(&Bs[0][srow1][scol1]) = ub1;
    }
    __syncthreads();

    for (int kt = 0; kt < ntiles; kt++) {
        const bool has_next = (kt + 1) < ntiles;
        if (has_next) {
            const long kb = (long)(kt + 1) * BK;
            pa0 = *reinterpret_cast<const float4*>(&A[(kb + srow0) * lda + m0 + scol0]);
            pa1 = *reinterpret_cast<const float4*>(&A[(kb + srow1) * lda + m0 + scol1]);
            pb0 = *reinterpret_cast<const float4*>(&B[(kb + srow0) * ldb + n0 + scol0]);
            pb1 = *reinterpret_cast<const float4*>(&B[(kb + srow1) * ldb + n0 + scol1]);
        }

#pragma unroll
        for (int ks = 0; ks < BK; ks += 8) {
            uint32_t af[4][4];
            uint32_t bf[4][2];
#pragma unroll
            for (int mt = 0; mt < 4; mt++) {
                const int mb = wm + mt * 16;
                af[mt][0] = As[buf][ks + tg    ][mb + g];
                af[mt][1] = As[buf][ks + tg    ][mb + g + 8];
                af[mt][2] = As[buf][ks + tg + 4][mb + g];
                af[mt][3] = As[buf][ks + tg + 4][mb + g + 8];
            }
#pragma unroll
            for (int nt = 0; nt < 4; nt++) {
                const int nb = wn + nt * 8;
                bf[nt][0] = Bs[buf][ks + tg    ][nb + g];
                bf[nt][1] = Bs[buf][ks + tg + 4][nb + g];
            }
#pragma unroll
            for (int mt = 0; mt < 4; mt++)
#pragma unroll
                for (int nt = 0; nt < 4; nt++)
                    mma_tf32(c[mt][nt], af[mt], bf[nt]);
        }

        if (has_next) {
            uint4 ua0 = {f2tf32(pa0.x), f2tf32(pa0.y), f2tf32(pa0.z), f2tf32(pa0.w)};
            uint4 ua1 = {f2tf32(pa1.x), f2tf32(pa1.y), f2tf32(pa1.z), f2tf32(pa1.w)};
            uint4 ub0 = {f2tf32(pb0.x), f2tf32(pb0.y), f2tf32(pb0.z), f2tf32(pb0.w)};
            uint4 ub1 = {f2tf32(pb1.x), f2tf32(pb1.y), f2tf32(pb1.z), f2tf32(pb1.w)};
            const int nb = buf ^ 1;
            *reinterpret_cast<uint4*>(&As[nb][srow0][scol0]) = ua0;
            *reinterpret_cast<uint4*>(&As[nb][srow1][scol1]) = ua1;
            *reinterpret_cast<uint4*>(&Bs[nb][srow0][scol0]) = ub0;
            *reinterpret_cast<uint4*>(&Bs[nb][srow1][scol1]) = ub1;
        }
        __syncthreads();
        buf ^= 1;
    }

#pragma unroll
    for (int mt = 0; mt < 4; mt++) {
        const int m = m0 + wm + mt * 16 + g;
        const float bv0 = bias ? bias[m]     : 0.0f;
        const float bv8 = bias ? bias[m + 8] : 0.0f;
#pragma unroll
        for (int nt = 0; nt < 4; nt++) {
            const int n = n0 + wn + nt * 8 + 2 * tg;
            float2 o0 = {c[mt][nt][0] + bv0, c[mt][nt][1] + bv0};
            float2 o1 = {c[mt][nt][2] + bv8, c[mt][nt][3] + bv8};
            if (round_out) {
                o0.x = __uint_as_float(f2tf32(o0.x));
                o0.y = __uint_as_float(f2tf32(o0.y));
                o1.x = __uint_as_float(f2tf32(o1.x));
                o1.y = __uint_as_float(f2tf32(o1.y));
            }
            *reinterpret_cast<float2*>(&C[(long)m * ldc + n])       = o0;
            *reinterpret_cast<float2*>(&C[(long)(m + 8) * ldc + n]) = o1;
        }
    }
}

// ======================= softmax stats (no write-back) =====================
__global__ __launch_bounds__(256) void softmax_stats()
{
    const int row = blockIdx.x;           // 0 .. BATCH*DIM-1
    const int b = row / DIM;
    const int r = row % DIM;
    const float* p = g_qkv + (long)b * FKV * LSEQ + (long)r * LSEQ;

    const int tid = threadIdx.x;
    float4 v[4];
    float mx = -1e30f;
#pragma unroll
    for (int i = 0; i < 4; i++) {
        v[i] = reinterpret_cast<const float4*>(p)[tid + i * 256];
        mx = fmaxf(mx, fmaxf(fmaxf(v[i].x, v[i].y), fmaxf(v[i].z, v[i].w)));
    }

    __shared__ float red[8];
#pragma unroll
    for (int o = 16; o; o >>= 1) mx = fmaxf(mx, __shfl_xor_sync(~0u, mx, o));
    if ((tid & 31) == 0) red[tid >> 5] = mx;
    __syncthreads();
    mx = red[0];
#pragma unroll
    for (int i = 1; i < 8; i++) mx = fmaxf(mx, red[i]);
    __syncthreads();

    float s = 0.0f;
#pragma unroll
    for (int i = 0; i < 4; i++) {
        s += expf(v[i].x - mx) + expf(v[i].y - mx)
           + expf(v[i].z - mx) + expf(v[i].w - mx);
    }
#pragma unroll
    for (int o = 16; o; o >>= 1) s += __shfl_xor_sync(~0u, s, o);
    if ((tid & 31) == 0) red[tid >> 5] = s;
    __syncthreads();
    if (tid == 0) {
        s = red[0];
#pragma unroll
        for (int i = 1; i < 8; i++) s += red[i];
        g_stats[row] = make_float2(mx, 1.0f / s);
    }
}

// ======================= ctx partials: tensor cores + fused softmax ========
#define CP 72
__global__ __launch_bounds__(256) void ctx_partial_tc()
{
    const int bh = blockIdx.x;
    const int split = blockIdx.y;
    const int b = bh >> 3, h = bh & 7;
    const float* Kp = g_qkv + (long)b * FKV * LSEQ + (long)(h * DH) * LSEQ;
    const float* Vp = g_qkv + (long)b * FKV * LSEQ + (long)(DIM + h * DH) * LSEQ;
    const int n0 = split * (LSEQ / NSPLIT);

    __shared__ uint32_t Ks[32][CP];
    __shared__ uint32_t Vs[32][CP];

    const int tid  = threadIdx.x;
    const int lane = tid & 31;
    const int g    = lane >> 2;
    const int tg   = lane & 3;
    const int warp = tid >> 5;
    const int wm   = (warp >> 2) * 32;
    const int wn   = (warp & 3) * 16;

    const int r = tid >> 2;
    const int q = tid & 3;
    const float m_r = g_stats[b * DIM + h * DH + r].x;

    float acc[2][2][4];
#pragma unroll
    for (int i = 0; i < 2; i++)
#pragma unroll
        for (int j = 0; j < 2; j++)
#pragma unroll
            for (int p = 0; p < 4; p++) acc[i][j][p] = 0.0f;

    float4 k0, k1, v0, v1;
    const float* kr = Kp + (long)r * LSEQ + n0 + q * 8;
    const float* vr = Vp + (long)r * LSEQ + n0 + q * 8;
    k0 = *reinterpret_cast<const float4*>(kr);
    k1 = *reinterpret_cast<const float4*>(kr + 4);
    v0 = *reinterpret_cast<const float4*>(vr);
    v1 = *reinterpret_cast<const float4*>(vr + 4);

    for (int c = 0; c < 8; c++) {
        const int nb = q * 8;
        Ks[nb    ][r] = f2tf32(expf(k0.x - m_r));
        Ks[nb + 1][r] = f2tf32(expf(k0.y - m_r));
        Ks[nb + 2][r] = f2tf32(expf(k0.z - m_r));
        Ks[nb + 3][r] = f2tf32(expf(k0.w - m_r));
        Ks[nb + 4][r] = f2tf32(expf(k1.x - m_r));
        Ks[nb + 5][r] = f2tf32(expf(k1.y - m_r));
        Ks[nb + 6][r] = f2tf32(expf(k1.z - m_r));
        Ks[nb + 7][r] = f2tf32(expf(k1.w - m_r));
        Vs[nb    ][r] = f2tf32(v0.x);
        Vs[nb + 1][r] = f2tf32(v0.y);
        Vs[nb + 2][r] = f2tf32(v0.z);
        Vs[nb + 3][r] = f2tf32(v0.w);
        Vs[nb + 4][r] = f2tf32(v1.x);
        Vs[nb + 5][r] = f2tf32(v1.y);
        Vs[nb + 6][r] = f2tf32(v1.z);
        Vs[nb + 7][r] = f2tf32(v1.w);
        __syncthreads();

        if (c + 1 < 8) {
            const float* krn = kr + (c + 1) * 32;
            const float* vrn = vr + (c + 1) * 32;
            k0 = *reinterpret_cast<const float4*>(krn);
            k1 = *reinterpret_cast<const float4*>(krn + 4);
            v0 = *reinterpret_cast<const float4*>(vrn);
            v1 = *reinterpret_cast<const float4*>(vrn + 4);
        }

#pragma unroll
        for (int ks = 0; ks < 32; ks += 8) {
            uint32_t af[2][4];
            uint32_t bf[2][2];
#pragma unroll
            for (int mt = 0; mt < 2; mt++) {
                const int mb = wm + mt * 16;
                af[mt][0] = Ks[ks + tg    ][mb + g];
                af[mt][1] = Ks[ks + tg    ][mb + g + 8];
                af[mt][2] = Ks[ks + tg + 4][mb + g];
                af[mt][3] = Ks[ks + tg + 4][mb + g + 8];
            }
#pragma unroll
            for (int nt = 0; nt < 2; nt++) {
                const int nbx = wn + nt * 8;
                bf[nt][0] = Vs[ks + tg    ][nbx + g];
                bf[nt][1] = Vs[ks + tg + 4][nbx + g];
            }
#pragma unroll
            for (int mt = 0; mt < 2; mt++)
#pragma unroll
                for (int nt = 0; nt < 2; nt++)
                    mma_tf32(acc[mt][nt], af[mt], bf[nt]);
        }
        __syncthreads();
    }

    float* cp = g_ctxp + ((long)bh * NSPLIT + split) * DH * DH;
#pragma unroll
    for (int mt = 0; mt < 2; mt++) {
        const int m = wm + mt * 16 + g;
        const float is0 = g_stats[b * DIM + h * DH + m].y;
        const float is8 = g_stats[b * DIM + h * DH + m + 8].y;
#pragma unroll
        for (int nt = 0; nt < 2; nt++) {
            const int n = wn + nt * 8 + 2 * tg;
            float2 o0 = {acc[mt][nt][0] * is0, acc[mt][nt][1] * is0};
            float2 o1 = {acc[mt][nt][2] * is8, acc[mt][nt][3] * is8};
            *reinterpret_cast<float2*>(&cp[(long)m * DH + n])       = o0;
            *reinterpret_cast<float2*>(&cp[(long)(m + 8) * DH + n]) = o1;
        }
    }
}

// ======================= parallel split reduce =============================
__global__ __launch_bounds__(256) void ctx_reduce()
{
    const int idx = blockIdx.x * 256 + threadIdx.x;
    const int bh = idx >> 12;
    const int i  = idx & 4095;
    float s = 0.0f;
#pragma unroll
    for (int sp = 0; sp < NSPLIT; sp++)
        s += g_ctxp[((long)bh * NSPLIT + sp) * DH * DH + i];
    g_ctx[(long)bh * DH * DH + i] = s;
}

// ======================= fold w_out into ctx ===============================
__global__ __launch_bounds__(256) void wctx_fold(const float* __restrict__ w_out)
{
    const int bh = blockIdx.x;
    const int b = bh / HEADS, h = bh % HEADS;
    __shared__ float cs[64][65];
    const int tid = threadIdx.x;

    const float* cp = g_ctx + (long)bh * DH * DH;
    for (int i = tid; i < DH * DH; i += 256) cs[i >> 6][i & 63] = cp[i];
    __syncthreads();

    float* outp = g_wctxT + (long)b * DIM * DIM + (long)(h * DH) * DIM;

    for (int cb = 0; cb < 2; cb++) {
        const int c = cb * 256 + tid;
        float w[64];
#pragma unroll
        for (int e = 0; e < 64; e++) w[e] = w_out[(h * DH + e) * DIM + c];
#pragma unroll 4
        for (int d = 0; d < 64; d++) {
            float s = 0.0f;
#pragma unroll
            for (int e = 0; e < 64; e++) s = fmaf(cs[d][e], w[e], s);
            outp[(long)d * DIM + c] = s * SCALE;
        }
    }
}

// ---------------------------------------------------------------------------
extern "C" void kernel_launch(void* const* d_in, const int* in_sizes, int n_in,
                              void* d_out, int out_size)
{
    const float* x      = (const float*)d_in[0];   // (B, 512, 4096)
    const float* w_qkv  = (const float*)d_in[1];   // (512, 1536)
    const float* w_out  = (const float*)d_in[2];   // (512, 512)
    const float* b_out  = (const float*)d_in[3];   // (512,)
    float* out = (float*)d_out;                    // (B, 512, 4096)

    float* qkv;
    float* xr;
    float* wkv;
    float* wctxT;
    float* wqT;
    float* M2;
    cudaGetSymbolAddress((void**)&qkv,   g_qkv);
    cudaGetSymbolAddress((void**)&xr,    g_xr);
    cudaGetSymbolAddress((void**)&wkv,   g_wkv);
    cudaGetSymbolAddress((void**)&wctxT, g_wctxT);
    cudaGetSymbolAddress((void**)&wqT,   g_wqT);
    cudaGetSymbolAddress((void**)&M2,    g_M2);

    cudaFuncSetAttribute(gemm_async, cudaFuncAttributeMaxDynamicSharedMemorySize, GA_SMEM);

    // 0) pre-round inputs (RNA tf32): x -> xr, w_kv slice -> wkv; wqT raw
    {
        const int n4 = BATCH * DIM * LSEQ / 4;
        rna_vec<<<(n4 + 255) / 256, 256>>>((const float4*)x, (float4*)xr, n4);
        rna_wkv<<<(DIM * FKV / 4) / 256, 256>>>(w_qkv);
        dim3 g(DIM / 32, DIM / 32, 1);
        transpose_k<<<g, 256>>>(w_qkv, wqT, DIM, DIM, F3);
    }

    // 1) k,v = W_kv^T @ x per batch  (async GEMM, pre-rounded operands)
    {
        dim3 grid(LSEQ / GA_BN, FKV / GA_BM, BATCH);
        gemm_async<<<grid, 256, GA_SMEM>>>(wkv, xr, qkv,
                                           FKV, LSEQ, LSEQ, DIM,
                                           0L, (long)DIM * LSEQ, (long)FKV * LSEQ,
                                           nullptr);
    }

    // 2) softmax stats per k row
    softmax_stats<<<BATCH * DIM, 256>>>();

    // 3) ctx partials via tensor cores with fused exp/normalize
    {
        dim3 grid(BATCH * HEADS, NSPLIT);
        ctx_partial_tc<<<grid, 256>>>();
    }

    // 3b) parallel reduce
    ctx_reduce<<<(BATCH * HEADS * DH * DH) / 256, 256>>>();

    // 4) fold w_out into ctx (includes SCALE)
    wctx_fold<<<BATCH * HEADS, 256>>>(w_out);

    // 5) M2 = wqT^T-fold (small; rounds output for the async GEMM)
    {
        dim3 grid(DIM / BN, DIM / BM, BATCH);
        gemm_tf32<<<grid, 256>>>(wqT, wctxT, M2,
                                 DIM, DIM, DIM, DIM,
                                 0L, (long)DIM * DIM, (long)DIM * DIM,
                                 nullptr, 1);
    }

    // 6) out = M2^T @ x + bias  (async GEMM, pre-rounded operands)
    {
        dim3 grid(LSEQ / GA_BN, DIM / GA_BM, BATCH);
        gemm_async<<<grid, 256, GA_SMEM>>>(M2, xr, out,
                                           DIM, LSEQ, LSEQ, DIM,
                                           (long)DIM * DIM, (long)DIM * LSEQ, (long)DIM * LSEQ,
                                           b_out);
    }
}

// round 15
// speedup vs baseline: 1.9621x; 1.1146x over previous
#include <cuda_runtime.h>
#include <math.h>
#include <stdint.h>

#define BATCH 8
#define DIM   512
#define HEADS 8
#define DH    64
#define LSEQ  4096
#define F3    1536            // 3 * HEADS * DIM_HEAD
#define FKV   1024            // k,v thirds only
#define SCALE 0.125f          // DH^-0.5
#define NSPLIT 16

// ---------------- scratch (device globals; no allocation allowed) ----------
__device__ float  g_qkv[(size_t)BATCH * FKV * LSEQ];                 // 134 MB (k,v raw)
__device__ float  g_xr[(size_t)BATCH * DIM * LSEQ];                  // 67 MB (x, RNA-rounded)
__device__ float  g_wkv[(size_t)DIM * FKV];                          // 2 MB (w kv slice, RNA)
__device__ float  g_ctxp[(size_t)BATCH * HEADS * NSPLIT * DH * DH];  // 16.8 MB
__device__ float  g_ctx[(size_t)BATCH * HEADS * DH * DH];            // 1 MB
__device__ float2 g_stats[(size_t)BATCH * DIM];                      // (max, 1/sumexp)
__device__ float  g_wctxT[(size_t)BATCH * DIM * DIM];                // 8 MB
__device__ float  g_wqT[(size_t)DIM * DIM];                          // 1 MB
__device__ float  g_M2[(size_t)BATCH * DIM * DIM];                   // 8 MB (RNA-rounded)

// ======================= helpers ==========================================
__device__ __forceinline__ uint32_t f2tf32(float x) {
    uint32_t u;
    asm("cvt.rna.tf32.f32 %0, %1;" : "=r"(u) : "f"(x));
    return u;
}

__device__ __forceinline__ void mma_tf32(float c[4], const uint32_t a[4], const uint32_t b[2]) {
    asm volatile(
        "mma.sync.aligned.m16n8k8.row.col.f32.tf32.tf32.f32 "
        "{%0,%1,%2,%3}, {%4,%5,%6,%7}, {%8,%9}, {%0,%1,%2,%3};"
        : "+f"(c[0]), "+f"(c[1]), "+f"(c[2]), "+f"(c[3])
        : "r"(a[0]), "r"(a[1]), "r"(a[2]), "r"(a[3]), "r"(b[0]), "r"(b[1]));
}

__device__ __forceinline__ uint32_t smem_u32(const void* p) {
    uint32_t a;
    asm("{ .reg .u64 t; cvta.to.shared.u64 t, %1; cvt.u32.u64 %0, t; }" : "=r"(a) : "l"(p));
    return a;
}
__device__ __forceinline__ void cp16(uint32_t dst, const void* src) {
    asm volatile("cp.async.cg.shared.global [%0], [%1], 16;" :: "r"(dst), "l"(src));
}

// ======================= RNA pre-rounding passes ===========================
__global__ __launch_bounds__(256) void rna_vec(const float4* __restrict__ in,
                                               float4* __restrict__ out, int n4)
{
    const int i = blockIdx.x * 256 + threadIdx.x;
    if (i < n4) {
        float4 v = in[i];
        v.x = __uint_as_float(f2tf32(v.x));
        v.y = __uint_as_float(f2tf32(v.y));
        v.z = __uint_as_float(f2tf32(v.z));
        v.w = __uint_as_float(f2tf32(v.w));
        out[i] = v;
    }
}

// copy+round w_qkv columns [512,1536) into contiguous (512 x 1024)
__global__ __launch_bounds__(256) void rna_wkv(const float* __restrict__ w)
{
    const int i = blockIdx.x * 256 + threadIdx.x;   // float4 units
    const int r = i >> 8;
    const int c = (i & 255) * 4;
    float4 v = *reinterpret_cast<const float4*>(&w[(long)r * F3 + DIM + c]);
    v.x = __uint_as_float(f2tf32(v.x));
    v.y = __uint_as_float(f2tf32(v.y));
    v.z = __uint_as_float(f2tf32(v.z));
    v.w = __uint_as_float(f2tf32(v.w));
    *reinterpret_cast<float4*>(&g_wkv[(long)r * FKV + c]) = v;
}

// ======================= transpose (wqT for GEMM2) ========================
__global__ __launch_bounds__(256) void transpose_k(
    const float* __restrict__ in, float* __restrict__ out,
    int R, int C, int ldin)
{
    __shared__ float t[32][33];
    const int c0 = blockIdx.x * 32;
    const int r0 = blockIdx.y * 32;
    const int tx = threadIdx.x & 31;
    const int ty = threadIdx.x >> 5;
#pragma unroll
    for (int i = 0; i < 4; i++)
        t[ty + i * 8][tx] = in[(long)(r0 + ty + i * 8) * ldin + c0 + tx];
    __syncthreads();
#pragma unroll
    for (int i = 0; i < 4; i++)
        out[(long)(c0 + ty + i * 8) * R + r0 + tx] = t[tx][ty + i * 8];
}

// ======================= big GEMM: cp.async 4-stage, 128x128, 2 CTA/SM =====
// C[m,n] = sum_k A[k,m]*B[k,n] (+bias[m]). Inputs MUST be pre-rounded tf32.
// 256 threads = 8 warps (2m x 4n), warp tile 64x32 (4x4 m16n8k8 tiles).
// Small acc footprint (64 regs) -> 2 CTAs/SM so barrier/LDS bubbles of one
// CTA are covered by the other CTA's MMA trains.
#define GA_BM 128
#define GA_BN 128
#define GA_BK 16
#define GA_W  136              // row stride in words (128 + 8 pad)
#define GA_AOFF(s) ((s) * (GA_BK * GA_W))
#define GA_BOFF(s) (4 * GA_BK * GA_W + (s) * (GA_BK * GA_W))
#define GA_SMEM (8 * GA_BK * GA_W * 4)   // 69632 B

__global__ __launch_bounds__(256, 2) void gemm_async(
    const float* __restrict__ A, const float* __restrict__ B,
    float* __restrict__ C,
    int lda, int ldb, int ldc, int K,
    long sA, long sB, long sC,
    const float* __restrict__ bias)
{
    extern __shared__ uint32_t sm[];
    const uint32_t sb = smem_u32(sm);

    A += (long)blockIdx.z * sA;
    B += (long)blockIdx.z * sB;
    C += (long)blockIdx.z * sC;

    const int m0 = blockIdx.y * GA_BM;
    const int n0 = blockIdx.x * GA_BN;

    const int tid  = threadIdx.x;
    const int lane = tid & 31;
    const int g    = lane >> 2;
    const int tg   = lane & 3;
    const int warp = tid >> 5;
    const int wm   = (warp >> 2) * 64;
    const int wn   = (warp & 3) * 32;

    const int NKT = K / GA_BK;

    auto stage = [&](int kt, int s) {
        const int k0 = kt * GA_BK;
#pragma unroll
        for (int i = 0; i < 2; i++) {            // A: 512 16B units
            const int u = tid + 256 * i;
            const int row = u >> 5, c4 = (u & 31) * 4;
            cp16(sb + (GA_AOFF(s) + row * GA_W + c4) * 4,
                 A + (long)(k0 + row) * lda + m0 + c4);
        }
#pragma unroll
        for (int j = 0; j < 2; j++) {            // B: 512 16B units
            const int u = tid + 256 * j;
            const int row = u >> 5, c4 = (u & 31) * 4;
            cp16(sb + (GA_BOFF(s) + row * GA_W + c4) * 4,
                 B + (long)(k0 + row) * ldb + n0 + c4);
        }
    };

    float acc[4][4][4];
#pragma unroll
    for (int i = 0; i < 4; i++)
#pragma unroll
        for (int j = 0; j < 4; j++)
#pragma unroll
            for (int q = 0; q < 4; q++) acc[i][j][q] = 0.0f;

    // prologue: 3 stages in flight
    stage(0, 0); asm volatile("cp.async.commit_group;" ::: "memory");
    stage(1, 1); asm volatile("cp.async.commit_group;" ::: "memory");
    stage(2, 2); asm volatile("cp.async.commit_group;" ::: "memory");

    for (int kt = 0; kt < NKT; kt++) {
        asm volatile("cp.async.wait_group 2;" ::: "memory");
        __syncthreads();
        // this sync also orders all warps' (kt-1) MMAs before stage() below
        // overwrites buffer (kt-1)&3 — no tail sync needed.

        if (kt + 3 < NKT) stage(kt + 3, (kt + 3) & 3);
        asm volatile("cp.async.commit_group;" ::: "memory");

        const uint32_t* SA = sm + GA_AOFF(kt & 3);
        const uint32_t* SB = sm + GA_BOFF(kt & 3);

#pragma unroll
        for (int ks = 0; ks < GA_BK; ks += 8) {
            uint32_t af[4][4];
            uint32_t bf[4][2];
#pragma unroll
            for (int mt = 0; mt < 4; mt++) {
                const int mb = wm + mt * 16;
                af[mt][0] = SA[(ks + tg    ) * GA_W + mb + g];
                af[mt][1] = SA[(ks + tg    ) * GA_W + mb + g + 8];
                af[mt][2] = SA[(ks + tg + 4) * GA_W + mb + g];
                af[mt][3] = SA[(ks + tg + 4) * GA_W + mb + g + 8];
            }
#pragma unroll
            for (int nt = 0; nt < 4; nt++) {
                const int nb = wn + nt * 8;
                bf[nt][0] = SB[(ks + tg    ) * GA_W + nb + g];
                bf[nt][1] = SB[(ks + tg + 4) * GA_W + nb + g];
            }
#pragma unroll
            for (int mt = 0; mt < 4; mt++)
#pragma unroll
                for (int nt = 0; nt < 4; nt++)
                    mma_tf32(acc[mt][nt], af[mt], bf[nt]);
        }
    }

#pragma unroll
    for (int mt = 0; mt < 4; mt++) {
        const int m = m0 + wm + mt * 16 + g;
        const float bv0 = bias ? bias[m]     : 0.0f;
        const float bv8 = bias ? bias[m + 8] : 0.0f;
#pragma unroll
        for (int nt = 0; nt < 4; nt++) {
            const int n = n0 + wn + nt * 8 + 2 * tg;
            float2 o0 = {acc[mt][nt][0] + bv0, acc[mt][nt][1] + bv0};
            float2 o1 = {acc[mt][nt][2] + bv8, acc[mt][nt][3] + bv8};
            *reinterpret_cast<float2*>(&C[(long)m * ldc + n])       = o0;
            *reinterpret_cast<float2*>(&C[(long)(m + 8) * ldc + n]) = o1;
        }
    }
}

// ======================= small GEMM (cvt staging) for M2 ===================
#define BM 128
#define BN 128
#define BK 16

__global__ __launch_bounds__(256, 2) void gemm_tf32(
    const float* __restrict__ A, const float* __restrict__ B,
    float* __restrict__ C,
    int lda, int ldb, int ldc, int K,
    long sA, long sB, long sC,
    const float* __restrict__ bias, int round_out)
{
    A += (long)blockIdx.z * sA;
    B += (long)blockIdx.z * sB;
    C += (long)blockIdx.z * sC;

    const int m0 = blockIdx.y * BM;
    const int n0 = blockIdx.x * BN;

    __shared__ uint32_t As[2][BK][BM + 4];
    __shared__ uint32_t Bs[2][BK][BN + 4];

    const int tid  = threadIdx.x;
    const int lane = tid & 31;
    const int g    = lane >> 2;
    const int tg   = lane & 3;
    const int warp = tid >> 5;
    const int wm   = (warp >> 2) * 64;
    const int wn   = (warp & 3) * 32;

    const int srow0 = tid >> 5;
    const int scol0 = (tid & 31) * 4;
    const int srow1 = 8 + (tid >> 5);
    const int scol1 = scol0;

    float c[4][4][4];
#pragma unroll
    for (int i = 0; i < 4; i++)
#pragma unroll
        for (int j = 0; j < 4; j++)
#pragma unroll
            for (int q = 0; q < 4; q++) c[i][j][q] = 0.0f;

    const int ntiles = K / BK;
    float4 pa0, pa1, pb0, pb1;

    pa0 = *reinterpret_cast<const float4*>(&A[(long)srow0 * lda + m0 + scol0]);
    pa1 = *reinterpret_cast<const float4*>(&A[(long)srow1 * lda + m0 + scol1]);
    pb0 = *reinterpret_cast<const float4*>(&B[(long)srow0 * ldb + n0 + scol0]);
    pb1 = *reinterpret_cast<const float4*>(&B[(long)srow1 * ldb + n0 + scol1]);

    int buf = 0;
    {
        uint4 ua0 = {f2tf32(pa0.x), f2tf32(pa0.y), f2tf32(pa0.z), f2tf32(pa0.w)};
        uint4 ua1 = {f2tf32(pa1.x), f2tf32(pa1.y), f2tf32(pa1.z), f2tf32(pa1.w)};
        uint4 ub0 = {f2tf32(pb0.x), f2tf32(pb0.y), f2tf32(pb0.z), f2tf32(pb0.w)};
        uint4 ub1 = {f2tf32(pb1.x), f2tf32(pb1.y), f2tf32(pb1.z), f2tf32(pb1.w)};
        *reinterpret_cast<uint4*>(&As[0][srow0][scol0]) = ua0;
        *reinterpret_cast<uint4*>(&As[0][srow1][scol1]) = ua1;
        *reinterpret_cast<uint4*>(&Bs[0][srow0][scol0]) = ub0;
        *reinterpret_cast<uint4*>(&Bs[0][srow1][scol1]) = ub1;
    }
    __syncthreads();

    for (int kt = 0; kt < ntiles; kt++) {
        const bool has_next = (kt + 1) < ntiles;
        if (has_next) {
            const long kb = (long)(kt + 1) * BK;
            pa0 = *reinterpret_cast<const float4*>(&A[(kb + srow0) * lda + m0 + scol0]);
            pa1 = *reinterpret_cast<const float4*>(&A[(kb + srow1) * lda + m0 + scol1]);
            pb0 = *reinterpret_cast<const float4*>(&B[(kb + srow0) * ldb + n0 + scol0]);
            pb1 = *reinterpret_cast<const float4*>(&B[(kb + srow1) * ldb + n0 + scol1]);
        }

#pragma unroll
        for (int ks = 0; ks < BK; ks += 8) {
            uint32_t af[4][4];
            uint32_t bf[4][2];
#pragma unroll
            for (int mt = 0; mt < 4; mt++) {
                const int mb = wm + mt * 16;
                af[mt][0] = As[buf][ks + tg    ][mb + g];
                af[mt][1] = As[buf][ks + tg    ][mb + g + 8];
                af[mt][2] = As[buf][ks + tg + 4][mb + g];
                af[mt][3] = As[buf][ks + tg + 4][mb + g + 8];
            }
#pragma unroll
            for (int nt = 0; nt < 4; nt++) {
                const int nb = wn + nt * 8;
                bf[nt][0] = Bs[buf][ks + tg    ][nb + g];
                bf[nt][1] = Bs[buf][ks + tg + 4][nb + g];
            }
#pragma unroll
            for (int mt = 0; mt < 4; mt++)
#pragma unroll
                for (int nt = 0; nt < 4; nt++)
                    mma_tf32(c[mt][nt], af[mt], bf[nt]);
        }

        if (has_next) {
            uint4 ua0 = {f2tf32(pa0.x), f2tf32(pa0.y), f2tf32(pa0.z), f2tf32(pa0.w)};
            uint4 ua1 = {f2tf32(pa1.x), f2tf32(pa1.y), f2tf32(pa1.z), f2tf32(pa1.w)};
            uint4 ub0 = {f2tf32(pb0.x), f2tf32(pb0.y), f2tf32(pb0.z), f2tf32(pb0.w)};
            uint4 ub1 = {f2tf32(pb1.x), f2tf32(pb1.y), f2tf32(pb1.z), f2tf32(pb1.w)};
            const int nb = buf ^ 1;
            *reinterpret_cast<uint4*>(&As[nb][srow0][scol0]) = ua0;
            *reinterpret_cast<uint4*>(&As[nb][srow1][scol1]) = ua1;
            *reinterpret_cast<uint4*>(&Bs[nb][srow0][scol0]) = ub0;
            *reinterpret_cast<uint4*>(&Bs[nb][srow1][scol1]) = ub1;
        }
        __syncthreads();
        buf ^= 1;
    }

#pragma unroll
    for (int mt = 0; mt < 4; mt++) {
        const int m = m0 + wm + mt * 16 + g;
        const float bv0 = bias ? bias[m]     : 0.0f;
        const float bv8 = bias ? bias[m + 8] : 0.0f;
#pragma unroll
        for (int nt = 0; nt < 4; nt++) {
            const int n = n0 + wn + nt * 8 + 2 * tg;
            float2 o0 = {c[mt][nt][0] + bv0, c[mt][nt][1] + bv0};
            float2 o1 = {c[mt][nt][2] + bv8, c[mt][nt][3] + bv8};
            if (round_out) {
                o0.x = __uint_as_float(f2tf32(o0.x));
                o0.y = __uint_as_float(f2tf32(o0.y));
                o1.x = __uint_as_float(f2tf32(o1.x));
                o1.y = __uint_as_float(f2tf32(o1.y));
            }
            *reinterpret_cast<float2*>(&C[(long)m * ldc + n])       = o0;
            *reinterpret_cast<float2*>(&C[(long)(m + 8) * ldc + n]) = o1;
        }
    }
}

// ======================= softmax stats (no write-back) =====================
__global__ __launch_bounds__(256) void softmax_stats()
{
    const int row = blockIdx.x;           // 0 .. BATCH*DIM-1
    const int b = row / DIM;
    const int r = row % DIM;
    const float* p = g_qkv + (long)b * FKV * LSEQ + (long)r * LSEQ;

    const int tid = threadIdx.x;
    float4 v[4];
    float mx = -1e30f;
#pragma unroll
    for (int i = 0; i < 4; i++) {
        v[i] = reinterpret_cast<const float4*>(p)[tid + i * 256];
        mx = fmaxf(mx, fmaxf(fmaxf(v[i].x, v[i].y), fmaxf(v[i].z, v[i].w)));
    }

    __shared__ float red[8];
#pragma unroll
    for (int o = 16; o; o >>= 1) mx = fmaxf(mx, __shfl_xor_sync(~0u, mx, o));
    if ((tid & 31) == 0) red[tid >> 5] = mx;
    __syncthreads();
    mx = red[0];
#pragma unroll
    for (int i = 1; i < 8; i++) mx = fmaxf(mx, red[i]);
    __syncthreads();

    float s = 0.0f;
#pragma unroll
    for (int i = 0; i < 4; i++) {
        s += expf(v[i].x - mx) + expf(v[i].y - mx)
           + expf(v[i].z - mx) + expf(v[i].w - mx);
    }
#pragma unroll
    for (int o = 16; o; o >>= 1) s += __shfl_xor_sync(~0u, s, o);
    if ((tid & 31) == 0) red[tid >> 5] = s;
    __syncthreads();
    if (tid == 0) {
        s = red[0];
#pragma unroll
        for (int i = 1; i < 8; i++) s += red[i];
        g_stats[row] = make_float2(mx, 1.0f / s);
    }
}

// ======================= ctx partials: tensor cores + fused softmax ========
#define CP 72
__global__ __launch_bounds__(256) void ctx_partial_tc()
{
    const int bh = blockIdx.x;
    const int split = blockIdx.y;
    const int b = bh >> 3, h = bh & 7;
    const float* Kp = g_qkv + (long)b * FKV * LSEQ + (long)(h * DH) * LSEQ;
    const float* Vp = g_qkv + (long)b * FKV * LSEQ + (long)(DIM + h * DH) * LSEQ;
    const int n0 = split * (LSEQ / NSPLIT);

    __shared__ uint32_t Ks[32][CP];
    __shared__ uint32_t Vs[32][CP];

    const int tid  = threadIdx.x;
    const int lane = tid & 31;
    const int g    = lane >> 2;
    const int tg   = lane & 3;
    const int warp = tid >> 5;
    const int wm   = (warp >> 2) * 32;
    const int wn   = (warp & 3) * 16;

    const int r = tid >> 2;
    const int q = tid & 3;
    const float m_r = g_stats[b * DIM + h * DH + r].x;

    float acc[2][2][4];
#pragma unroll
    for (int i = 0; i < 2; i++)
#pragma unroll
        for (int j = 0; j < 2; j++)
#pragma unroll
            for (int p = 0; p < 4; p++) acc[i][j][p] = 0.0f;

    float4 k0, k1, v0, v1;
    const float* kr = Kp + (long)r * LSEQ + n0 + q * 8;
    const float* vr = Vp + (long)r * LSEQ + n0 + q * 8;
    k0 = *reinterpret_cast<const float4*>(kr);
    k1 = *reinterpret_cast<const float4*>(kr + 4);
    v0 = *reinterpret_cast<const float4*>(vr);
    v1 = *reinterpret_cast<const float4*>(vr + 4);

    for (int c = 0; c < 8; c++) {
        const int nb = q * 8;
        Ks[nb    ][r] = f2tf32(expf(k0.x - m_r));
        Ks[nb + 1][r] = f2tf32(expf(k0.y - m_r));
        Ks[nb + 2][r] = f2tf32(expf(k0.z - m_r));
        Ks[nb + 3][r] = f2tf32(expf(k0.w - m_r));
        Ks[nb + 4][r] = f2tf32(expf(k1.x - m_r));
        Ks[nb + 5][r] = f2tf32(expf(k1.y - m_r));
        Ks[nb + 6][r] = f2tf32(expf(k1.z - m_r));
        Ks[nb + 7][r] = f2tf32(expf(k1.w - m_r));
        Vs[nb    ][r] = f2tf32(v0.x);
        Vs[nb + 1][r] = f2tf32(v0.y);
        Vs[nb + 2][r] = f2tf32(v0.z);
        Vs[nb + 3][r] = f2tf32(v0.w);
        Vs[nb + 4][r] = f2tf32(v1.x);
        Vs[nb + 5][r] = f2tf32(v1.y);
        Vs[nb + 6][r] = f2tf32(v1.z);
        Vs[nb + 7][r] = f2tf32(v1.w);
        __syncthreads();

        if (c + 1 < 8) {
            const float* krn = kr + (c + 1) * 32;
            const float* vrn = vr + (c + 1) * 32;
            k0 = *reinterpret_cast<const float4*>(krn);
            k1 = *reinterpret_cast<const float4*>(krn + 4);
            v0 = *reinterpret_cast<const float4*>(vrn);
            v1 = *reinterpret_cast<const float4*>(vrn + 4);
        }

#pragma unroll
        for (int ks = 0; ks < 32; ks += 8) {
            uint32_t af[2][4];
            uint32_t bf[2][2];
#pragma unroll
            for (int mt = 0; mt < 2; mt++) {
                const int mb = wm + mt * 16;
                af[mt][0] = Ks[ks + tg    ][mb + g];
                af[mt][1] = Ks[ks + tg    ][mb + g + 8];
                af[mt][2] = Ks[ks + tg + 4][mb + g];
                af[mt][3] = Ks[ks + tg + 4][mb + g + 8];
            }
#pragma unroll
            for (int nt = 0; nt < 2; nt++) {
                const int nbx = wn + nt * 8;
                bf[nt][0] = Vs[ks + tg    ][nbx + g];
                bf[nt][1] = Vs[ks + tg + 4][nbx + g];
            }
#pragma unroll
            for (int mt = 0; mt < 2; mt++)
#pragma unroll
                for (int nt = 0; nt < 2; nt++)
                    mma_tf32(acc[mt][nt], af[mt], bf[nt]);
        }
        __syncthreads();
    }

    float* cp = g_ctxp + ((long)bh * NSPLIT + split) * DH * DH;
#pragma unroll
    for (int mt = 0; mt < 2; mt++) {
        const int m = wm + mt * 16 + g;
        const float is0 = g_stats[b * DIM + h * DH + m].y;
        const float is8 = g_stats[b * DIM + h * DH + m + 8].y;
#pragma unroll
        for (int nt = 0; nt < 2; nt++) {
            const int n = wn + nt * 8 + 2 * tg;
            float2 o0 = {acc[mt][nt][0] * is0, acc[mt][nt][1] * is0};
            float2 o1 = {acc[mt][nt][2] * is8, acc[mt][nt][3] * is8};
            *reinterpret_cast<float2*>(&cp[(long)m * DH + n])       = o0;
            *reinterpret_cast<float2*>(&cp[(long)(m + 8) * DH + n]) = o1;
        }
    }
}

// ======================= parallel split reduce =============================
__global__ __launch_bounds__(256) void ctx_reduce()
{
    const int idx = blockIdx.x * 256 + threadIdx.x;
    const int bh = idx >> 12;
    const int i  = idx & 4095;
    float s = 0.0f;
#pragma unroll
    for (int sp = 0; sp < NSPLIT; sp++)
        s += g_ctxp[((long)bh * NSPLIT + sp) * DH * DH + i];
    g_ctx[(long)bh * DH * DH + i] = s;
}

// ======================= fold w_out into ctx ===============================
__global__ __launch_bounds__(256) void wctx_fold(const float* __restrict__ w_out)
{
    const int bh = blockIdx.x;
    const int b = bh / HEADS, h = bh % HEADS;
    __shared__ float cs[64][65];
    const int tid = threadIdx.x;

    const float* cp = g_ctx + (long)bh * DH * DH;
    for (int i = tid; i < DH * DH; i += 256) cs[i >> 6][i & 63] = cp[i];
    __syncthreads();

    float* outp = g_wctxT + (long)b * DIM * DIM + (long)(h * DH) * DIM;

    for (int cb = 0; cb < 2; cb++) {
        const int c = cb * 256 + tid;
        float w[64];
#pragma unroll
        for (int e = 0; e < 64; e++) w[e] = w_out[(h * DH + e) * DIM + c];
#pragma unroll 4
        for (int d = 0; d < 64; d++) {
            float s = 0.0f;
#pragma unroll
            for (int e = 0; e < 64; e++) s = fmaf(cs[d][e], w[e], s);
            outp[(long)d * DIM + c] = s * SCALE;
        }
    }
}

// ---------------------------------------------------------------------------
extern "C" void kernel_launch(void* const* d_in, const int* in_sizes, int n_in,
                              void* d_out, int out_size)
{
    const float* x      = (const float*)d_in[0];   // (B, 512, 4096)
    const float* w_qkv  = (const float*)d_in[1];   // (512, 1536)
    const float* w_out  = (const float*)d_in[2];   // (512, 512)
    const float* b_out  = (const float*)d_in[3];   // (512,)
    float* out = (float*)d_out;                    // (B, 512, 4096)

    float* qkv;
    float* xr;
    float* wkv;
    float* wctxT;
    float* wqT;
    float* M2;
    cudaGetSymbolAddress((void**)&qkv,   g_qkv);
    cudaGetSymbolAddress((void**)&xr,    g_xr);
    cudaGetSymbolAddress((void**)&wkv,   g_wkv);
    cudaGetSymbolAddress((void**)&wctxT, g_wctxT);
    cudaGetSymbolAddress((void**)&wqT,   g_wqT);
    cudaGetSymbolAddress((void**)&M2,    g_M2);

    cudaFuncSetAttribute(gemm_async, cudaFuncAttributeMaxDynamicSharedMemorySize, GA_SMEM);

    // 0) pre-round inputs (RNA tf32): x -> xr, w_kv slice -> wkv; wqT raw
    {
        const int n4 = BATCH * DIM * LSEQ / 4;
        rna_vec<<<(n4 + 255) / 256, 256>>>((const float4*)x, (float4*)xr, n4);
        rna_wkv<<<(DIM * FKV / 4) / 256, 256>>>(w_qkv);
        dim3 g(DIM / 32, DIM / 32, 1);
        transpose_k<<<g, 256>>>(w_qkv, wqT, DIM, DIM, F3);
    }

    // 1) k,v = W_kv^T @ x per batch  (async GEMM, 2 CTA/SM)
    {
        dim3 grid(LSEQ / GA_BN, FKV / GA_BM, BATCH);
        gemm_async<<<grid, 256, GA_SMEM>>>(wkv, xr, qkv,
                                           FKV, LSEQ, LSEQ, DIM,
                                           0L, (long)DIM * LSEQ, (long)FKV * LSEQ,
                                           nullptr);
    }

    // 2) softmax stats per k row
    softmax_stats<<<BATCH * DIM, 256>>>();

    // 3) ctx partials via tensor cores with fused exp/normalize
    {
        dim3 grid(BATCH * HEADS, NSPLIT);
        ctx_partial_tc<<<grid, 256>>>();
    }

    // 3b) parallel reduce
    ctx_reduce<<<(BATCH * HEADS * DH * DH) / 256, 256>>>();

    // 4) fold w_out into ctx (includes SCALE)
    wctx_fold<<<BATCH * HEADS, 256>>>(w_out);

    // 5) M2 = wqT^T-fold (small; rounds output for the async GEMM)
    {
        dim3 grid(DIM / BN, DIM / BM, BATCH);
        gemm_tf32<<<grid, 256>>>(wqT, wctxT, M2,
                                 DIM, DIM, DIM, DIM,
                                 0L, (long)DIM * DIM, (long)DIM * DIM,
                                 nullptr, 1);
    }

    // 6) out = M2^T @ x + bias  (async GEMM, 2 CTA/SM)
    {
        dim3 grid(LSEQ / GA_BN, DIM / GA_BM, BATCH);
        gemm_async<<<grid, 256, GA_SMEM>>>(M2, xr, out,
                                           DIM, LSEQ, LSEQ, DIM,
                                           (long)DIM * DIM, (long)DIM * LSEQ, (long)DIM * LSEQ,
                                           b_out);
    }
}

// round 17
// speedup vs baseline: 1.9850x; 1.0117x over previous
#include <cuda_runtime.h>
#include <math.h>
#include <stdint.h>

#define BATCH 8
#define DIM   512
#define HEADS 8
#define DH    64
#define LSEQ  4096
#define F3    1536            // 3 * HEADS * DIM_HEAD
#define FKV   1024            // k,v thirds only
#define SCALE 0.125f          // DH^-0.5
#define NSPLIT 16

// ---------------- scratch (device globals; no allocation allowed) ----------
__device__ float  g_qkv[(size_t)BATCH * FKV * LSEQ];                 // 134 MB (k,v raw)
__device__ float  g_xr[(size_t)BATCH * DIM * LSEQ];                  // 67 MB (x, RNA-rounded)
__device__ float  g_wkv[(size_t)DIM * FKV];                          // 2 MB (w kv slice, RNA)
__device__ float  g_ctxp[(size_t)BATCH * HEADS * NSPLIT * DH * DH];  // 16.8 MB
__device__ float  g_ctx[(size_t)BATCH * HEADS * DH * DH];            // 1 MB
__device__ float2 g_stats[(size_t)BATCH * DIM];                      // (max, 1/sumexp)
__device__ float  g_wctxT[(size_t)BATCH * DIM * DIM];                // 8 MB
__device__ float  g_wqT[(size_t)DIM * DIM];                          // 1 MB
__device__ float  g_M2[(size_t)BATCH * DIM * DIM];                   // 8 MB (RNA-rounded)

// ======================= helpers ==========================================
__device__ __forceinline__ uint32_t f2tf32(float x) {
    uint32_t u;
    asm("cvt.rna.tf32.f32 %0, %1;" : "=r"(u) : "f"(x));
    return u;
}

__device__ __forceinline__ void mma_tf32(float c[4], const uint32_t a[4], const uint32_t b[2]) {
    asm volatile(
        "mma.sync.aligned.m16n8k8.row.col.f32.tf32.tf32.f32 "
        "{%0,%1,%2,%3}, {%4,%5,%6,%7}, {%8,%9}, {%0,%1,%2,%3};"
        : "+f"(c[0]), "+f"(c[1]), "+f"(c[2]), "+f"(c[3])
        : "r"(a[0]), "r"(a[1]), "r"(a[2]), "r"(a[3]), "r"(b[0]), "r"(b[1]));
}

__device__ __forceinline__ uint32_t smem_u32(const void* p) {
    uint32_t a;
    asm("{ .reg .u64 t; cvta.to.shared.u64 t, %1; cvt.u32.u64 %0, t; }" : "=r"(a) : "l"(p));
    return a;
}
__device__ __forceinline__ void cp16(uint32_t dst, const void* src) {
    asm volatile("cp.async.cg.shared.global [%0], [%1], 16;" :: "r"(dst), "l"(src));
}

// ======================= RNA pre-rounding passes ===========================
__global__ __launch_bounds__(256) void rna_vec(const float4* __restrict__ in,
                                               float4* __restrict__ out, int n4)
{
    const int i = blockIdx.x * 256 + threadIdx.x;
    if (i < n4) {
        float4 v = in[i];
        v.x = __uint_as_float(f2tf32(v.x));
        v.y = __uint_as_float(f2tf32(v.y));
        v.z = __uint_as_float(f2tf32(v.z));
        v.w = __uint_as_float(f2tf32(v.w));
        out[i] = v;
    }
}

// copy+round w_qkv columns [512,1536) into contiguous (512 x 1024)
__global__ __launch_bounds__(256) void rna_wkv(const float* __restrict__ w)
{
    const int i = blockIdx.x * 256 + threadIdx.x;   // float4 units
    const int r = i >> 8;
    const int c = (i & 255) * 4;
    float4 v = *reinterpret_cast<const float4*>(&w[(long)r * F3 + DIM + c]);
    v.x = __uint_as_float(f2tf32(v.x));
    v.y = __uint_as_float(f2tf32(v.y));
    v.z = __uint_as_float(f2tf32(v.z));
    v.w = __uint_as_float(f2tf32(v.w));
    *reinterpret_cast<float4*>(&g_wkv[(long)r * FKV + c]) = v;
}

// ======================= transpose (wqT for GEMM2) ========================
__global__ __launch_bounds__(256) void transpose_k(
    const float* __restrict__ in, float* __restrict__ out,
    int R, int C, int ldin)
{
    __shared__ float t[32][33];
    const int c0 = blockIdx.x * 32;
    const int r0 = blockIdx.y * 32;
    const int tx = threadIdx.x & 31;
    const int ty = threadIdx.x >> 5;
#pragma unroll
    for (int i = 0; i < 4; i++)
        t[ty + i * 8][tx] = in[(long)(r0 + ty + i * 8) * ldin + c0 + tx];
    __syncthreads();
#pragma unroll
    for (int i = 0; i < 4; i++)
        out[(long)(c0 + ty + i * 8) * R + r0 + tx] = t[tx][ty + i * 8];
}

// ======================= big GEMM: cp.async 4-stage, 128x128 ===============
// C[m,n] = sum_k A[k,m]*B[k,n] (+bias[m]). Inputs MUST be pre-rounded tf32.
// 128 threads = 4 warps (2m x 2n), warp tile 64x64 (4x8 m16n8k8 tiles).
// 2 CTAs/SM -> each SMSP carries 2 INDEPENDENT warps (different CTAs):
// one CTA's barrier/LDS bubbles covered by the other's 64-MMA trains,
// while the fat warp tile keeps LDS:MMA at 1.0.
#define GA_BM 128
#define GA_BN 128
#define GA_BK 16
#define GA_W  136              // row stride in words (128 + 8 pad)
#define GA_AOFF(s) ((s) * (GA_BK * GA_W))
#define GA_BOFF(s) (4 * GA_BK * GA_W + (s) * (GA_BK * GA_W))
#define GA_SMEM (8 * GA_BK * GA_W * 4)   // 69632 B

__global__ __launch_bounds__(128, 2) void gemm_async(
    const float* __restrict__ A, const float* __restrict__ B,
    float* __restrict__ C,
    int lda, int ldb, int ldc, int K,
    long sA, long sB, long sC,
    const float* __restrict__ bias)
{
    extern __shared__ uint32_t sm[];
    const uint32_t sb = smem_u32(sm);

    A += (long)blockIdx.z * sA;
    B += (long)blockIdx.z * sB;
    C += (long)blockIdx.z * sC;

    const int m0 = blockIdx.y * GA_BM;
    const int n0 = blockIdx.x * GA_BN;

    const int tid  = threadIdx.x;
    const int lane = tid & 31;
    const int g    = lane >> 2;
    const int tg   = lane & 3;
    const int warp = tid >> 5;            // 0..3
    const int wm   = (warp >> 1) * 64;    // 2 warp rows
    const int wn   = (warp & 1) * 64;     // 2 warp cols

    const int NKT = K / GA_BK;

    auto stage = [&](int kt, int s) {
        const int k0 = kt * GA_BK;
#pragma unroll
        for (int i = 0; i < 4; i++) {            // A: 512 16B units
            const int u = tid + 128 * i;
            const int row = u >> 5, c4 = (u & 31) * 4;
            cp16(sb + (GA_AOFF(s) + row * GA_W + c4) * 4,
                 A + (long)(k0 + row) * lda + m0 + c4);
        }
#pragma unroll
        for (int j = 0; j < 4; j++) {            // B: 512 16B units
            const int u = tid + 128 * j;
            const int row = u >> 5, c4 = (u & 31) * 4;
            cp16(sb + (GA_BOFF(s) + row * GA_W + c4) * 4,
                 B + (long)(k0 + row) * ldb + n0 + c4);
        }
    };

    float acc[4][8][4];
#pragma unroll
    for (int i = 0; i < 4; i++)
#pragma unroll
        for (int j = 0; j < 8; j++)
#pragma unroll
            for (int q = 0; q < 4; q++) acc[i][j][q] = 0.0f;

    // prologue: 3 stages in flight
    stage(0, 0); asm volatile("cp.async.commit_group;" ::: "memory");
    stage(1, 1); asm volatile("cp.async.commit_group;" ::: "memory");
    stage(2, 2); asm volatile("cp.async.commit_group;" ::: "memory");

    for (int kt = 0; kt < NKT; kt++) {
        asm volatile("cp.async.wait_group 2;" ::: "memory");
        __syncthreads();
        // this sync also orders all warps' (kt-1) MMAs before stage() below
        // overwrites buffer (kt-1)&3 — no tail sync needed.

        if (kt + 3 < NKT) stage(kt + 3, (kt + 3) & 3);
        asm volatile("cp.async.commit_group;" ::: "memory");

        const uint32_t* SA = sm + GA_AOFF(kt & 3);
        const uint32_t* SB = sm + GA_BOFF(kt & 3);

#pragma unroll
        for (int ks = 0; ks < GA_BK; ks += 8) {
            uint32_t af[4][4];
            uint32_t bf[8][2];
#pragma unroll
            for (int mt = 0; mt < 4; mt++) {
                const int mb = wm + mt * 16;
                af[mt][0] = SA[(ks + tg    ) * GA_W + mb + g];
                af[mt][1] = SA[(ks + tg    ) * GA_W + mb + g + 8];
                af[mt][2] = SA[(ks + tg + 4) * GA_W + mb + g];
                af[mt][3] = SA[(ks + tg + 4) * GA_W + mb + g + 8];
            }
#pragma unroll
            for (int nt = 0; nt < 8; nt++) {
                const int nb = wn + nt * 8;
                bf[nt][0] = SB[(ks + tg    ) * GA_W + nb + g];
                bf[nt][1] = SB[(ks + tg + 4) * GA_W + nb + g];
            }
#pragma unroll
            for (int mt = 0; mt < 4; mt++)
#pragma unroll
                for (int nt = 0; nt < 8; nt++)
                    mma_tf32(acc[mt][nt], af[mt], bf[nt]);
        }
    }

#pragma unroll
    for (int mt = 0; mt < 4; mt++) {
        const int m = m0 + wm + mt * 16 + g;
        const float bv0 = bias ? bias[m]     : 0.0f;
        const float bv8 = bias ? bias[m + 8] : 0.0f;
#pragma unroll
        for (int nt = 0; nt < 8; nt++) {
            const int n = n0 + wn + nt * 8 + 2 * tg;
            float2 o0 = {acc[mt][nt][0] + bv0, acc[mt][nt][1] + bv0};
            float2 o1 = {acc[mt][nt][2] + bv8, acc[mt][nt][3] + bv8};
            *reinterpret_cast<float2*>(&C[(long)m * ldc + n])       = o0;
            *reinterpret_cast<float2*>(&C[(long)(m + 8) * ldc + n]) = o1;
        }
    }
}

// ======================= small GEMM (cvt staging) for M2 ===================
#define BM 128
#define BN 128
#define BK 16

__global__ __launch_bounds__(256, 2) void gemm_tf32(
    const float* __restrict__ A, const float* __restrict__ B,
    float* __restrict__ C,
    int lda, int ldb, int ldc, int K,
    long sA, long sB, long sC,
    const float* __restrict__ bias, int round_out)
{
    A += (long)blockIdx.z * sA;
    B += (long)blockIdx.z * sB;
    C += (long)blockIdx.z * sC;

    const int m0 = blockIdx.y * BM;
    const int n0 = blockIdx.x * BN;

    __shared__ uint32_t As[2][BK][BM + 4];
    __shared__ uint32_t Bs[2][BK][BN + 4];

    const int tid  = threadIdx.x;
    const int lane = tid & 31;
    const int g    = lane >> 2;
    const int tg   = lane & 3;
    const int warp = tid >> 5;
    const int wm   = (warp >> 2) * 64;
    const int wn   = (warp & 3) * 32;

    const int srow0 = tid >> 5;
    const int scol0 = (tid & 31) * 4;
    const int srow1 = 8 + (tid >> 5);
    const int scol1 = scol0;

    float c[4][4][4];
#pragma unroll
    for (int i = 0; i < 4; i++)
#pragma unroll
        for (int j = 0; j < 4; j++)
#pragma unroll
            for (int q = 0; q < 4; q++) c[i][j][q] = 0.0f;

    const int ntiles = K / BK;
    float4 pa0, pa1, pb0, pb1;

    pa0 = *reinterpret_cast<const float4*>(&A[(long)srow0 * lda + m0 + scol0]);
    pa1 = *reinterpret_cast<const float4*>(&A[(long)srow1 * lda + m0 + scol1]);
    pb0 = *reinterpret_cast<const float4*>(&B[(long)srow0 * ldb + n0 + scol0]);
    pb1 = *reinterpret_cast<const float4*>(&B[(long)srow1 * ldb + n0 + scol1]);

    int buf = 0;
    {
        uint4 ua0 = {f2tf32(pa0.x), f2tf32(pa0.y), f2tf32(pa0.z), f2tf32(pa0.w)};
        uint4 ua1 = {f2tf32(pa1.x), f2tf32(pa1.y), f2tf32(pa1.z), f2tf32(pa1.w)};
        uint4 ub0 = {f2tf32(pb0.x), f2tf32(pb0.y), f2tf32(pb0.z), f2tf32(pb0.w)};
        uint4 ub1 = {f2tf32(pb1.x), f2tf32(pb1.y), f2tf32(pb1.z), f2tf32(pb1.w)};
        *reinterpret_cast<uint4*>(&As[0][srow0][scol0]) = ua0;
        *reinterpret_cast<uint4*>(&As[0][srow1][scol1]) = ua1;
        *reinterpret_cast<uint4*>(&Bs[0][srow0][scol0]) = ub0;
        *reinterpret_cast<uint4*>(&Bs[0][srow1][scol1]) = ub1;
    }
    __syncthreads();

    for (int kt = 0; kt < ntiles; kt++) {
        const bool has_next = (kt + 1) < ntiles;
        if (has_next) {
            const long kb = (long)(kt + 1) * BK;
            pa0 = *reinterpret_cast<const float4*>(&A[(kb + srow0) * lda + m0 + scol0]);
            pa1 = *reinterpret_cast<const float4*>(&A[(kb + srow1) * lda + m0 + scol1]);
            pb0 = *reinterpret_cast<const float4*>(&B[(kb + srow0) * ldb + n0 + scol0]);
            pb1 = *reinterpret_cast<const float4*>(&B[(kb + srow1) * ldb + n0 + scol1]);
        }

#pragma unroll
        for (int ks = 0; ks < BK; ks += 8) {
            uint32_t af[4][4];
            uint32_t bf[4][2];
#pragma unroll
            for (int mt = 0; mt < 4; mt++) {
                const int mb = wm + mt * 16;
                af[mt][0] = As[buf][ks + tg    ][mb + g];
                af[mt][1] = As[buf][ks + tg    ][mb + g + 8];
                af[mt][2] = As[buf][ks + tg + 4][mb + g];
                af[mt][3] = As[buf][ks + tg + 4][mb + g + 8];
            }
#pragma unroll
            for (int nt = 0; nt < 4; nt++) {
                const int nb = wn + nt * 8;
                bf[nt][0] = Bs[buf][ks + tg    ][nb + g];
                bf[nt][1] = Bs[buf][ks + tg + 4][nb + g];
            }
#pragma unroll
            for (int mt = 0; mt < 4; mt++)
#pragma unroll
                for (int nt = 0; nt < 4; nt++)
                    mma_tf32(c[mt][nt], af[mt], bf[nt]);
        }

        if (has_next) {
            uint4 ua0 = {f2tf32(pa0.x), f2tf32(pa0.y), f2tf32(pa0.z), f2tf32(pa0.w)};
            uint4 ua1 = {f2tf32(pa1.x), f2tf32(pa1.y), f2tf32(pa1.z), f2tf32(pa1.w)};
            uint4 ub0 = {f2tf32(pb0.x), f2tf32(pb0.y), f2tf32(pb0.z), f2tf32(pb0.w)};
            uint4 ub1 = {f2tf32(pb1.x), f2tf32(pb1.y), f2tf32(pb1.z), f2tf32(pb1.w)};
            const int nb = buf ^ 1;
            *reinterpret_cast<uint4*>(&As[nb][srow0][scol0]) = ua0;
            *reinterpret_cast<uint4*>(&As[nb][srow1][scol1]) = ua1;
            *reinterpret_cast<uint4*>(&Bs[nb][srow0][scol0]) = ub0;
            *reinterpret_cast<uint4*>(&Bs[nb][srow1][scol1]) = ub1;
        }
        __syncthreads();
        buf ^= 1;
    }

#pragma unroll
    for (int mt = 0; mt < 4; mt++) {
        const int m = m0 + wm + mt * 16 + g;
        const float bv0 = bias ? bias[m]     : 0.0f;
        const float bv8 = bias ? bias[m + 8] : 0.0f;
#pragma unroll
        for (int nt = 0; nt < 4; nt++) {
            const int n = n0 + wn + nt * 8 + 2 * tg;
            float2 o0 = {c[mt][nt][0] + bv0, c[mt][nt][1] + bv0};
            float2 o1 = {c[mt][nt][2] + bv8, c[mt][nt][3] + bv8};
            if (round_out) {
                o0.x = __uint_as_float(f2tf32(o0.x));
                o0.y = __uint_as_float(f2tf32(o0.y));
                o1.x = __uint_as_float(f2tf32(o1.x));
                o1.y = __uint_as_float(f2tf32(o1.y));
            }
            *reinterpret_cast<float2*>(&C[(long)m * ldc + n])       = o0;
            *reinterpret_cast<float2*>(&C[(long)(m + 8) * ldc + n]) = o1;
        }
    }
}

// ======================= softmax stats (no write-back) =====================
__global__ __launch_bounds__(256) void softmax_stats()
{
    const int row = blockIdx.x;           // 0 .. BATCH*DIM-1
    const int b = row / DIM;
    const int r = row % DIM;
    const float* p = g_qkv + (long)b * FKV * LSEQ + (long)r * LSEQ;

    const int tid = threadIdx.x;
    float4 v[4];
    float mx = -1e30f;
#pragma unroll
    for (int i = 0; i < 4; i++) {
        v[i] = reinterpret_cast<const float4*>(p)[tid + i * 256];
        mx = fmaxf(mx, fmaxf(fmaxf(v[i].x, v[i].y), fmaxf(v[i].z, v[i].w)));
    }

    __shared__ float red[8];
#pragma unroll
    for (int o = 16; o; o >>= 1) mx = fmaxf(mx, __shfl_xor_sync(~0u, mx, o));
    if ((tid & 31) == 0) red[tid >> 5] = mx;
    __syncthreads();
    mx = red[0];
#pragma unroll
    for (int i = 1; i < 8; i++) mx = fmaxf(mx, red[i]);
    __syncthreads();

    float s = 0.0f;
#pragma unroll
    for (int i = 0; i < 4; i++) {
        s += expf(v[i].x - mx) + expf(v[i].y - mx)
           + expf(v[i].z - mx) + expf(v[i].w - mx);
    }
#pragma unroll
    for (int o = 16; o; o >>= 1) s += __shfl_xor_sync(~0u, s, o);
    if ((tid & 31) == 0) red[tid >> 5] = s;
    __syncthreads();
    if (tid == 0) {
        s = red[0];
#pragma unroll
        for (int i = 1; i < 8; i++) s += red[i];
        g_stats[row] = make_float2(mx, 1.0f / s);
    }
}

// ======================= ctx partials: tensor cores + fused softmax ========
#define CP 72
__global__ __launch_bounds__(256) void ctx_partial_tc()
{
    const int bh = blockIdx.x;
    const int split = blockIdx.y;
    const int b = bh >> 3, h = bh & 7;
    const float* Kp = g_qkv + (long)b * FKV * LSEQ + (long)(h * DH) * LSEQ;
    const float* Vp = g_qkv + (long)b * FKV * LSEQ + (long)(DIM + h * DH) * LSEQ;
    const int n0 = split * (LSEQ / NSPLIT);

    __shared__ uint32_t Ks[32][CP];
    __shared__ uint32_t Vs[32][CP];

    const int tid  = threadIdx.x;
    const int lane = tid & 31;
    const int g    = lane >> 2;
    const int tg   = lane & 3;
    const int warp = tid >> 5;
    const int wm   = (warp >> 2) * 32;
    const int wn   = (warp & 3) * 16;

    const int r = tid >> 2;
    const int q = tid & 3;
    const float m_r = g_stats[b * DIM + h * DH + r].x;

    float acc[2][2][4];
#pragma unroll
    for (int i = 0; i < 2; i++)
#pragma unroll
        for (int j = 0; j < 2; j++)
#pragma unroll
            for (int p = 0; p < 4; p++) acc[i][j][p] = 0.0f;

    float4 k0, k1, v0, v1;
    const float* kr = Kp + (long)r * LSEQ + n0 + q * 8;
    const float* vr = Vp + (long)r * LSEQ + n0 + q * 8;
    k0 = *reinterpret_cast<const float4*>(kr);
    k1 = *reinterpret_cast<const float4*>(kr + 4);
    v0 = *reinterpret_cast<const float4*>(vr);
    v1 = *reinterpret_cast<const float4*>(vr + 4);

    for (int c = 0; c < 8; c++) {
        const int nb = q * 8;
        Ks[nb    ][r] = f2tf32(expf(k0.x - m_r));
        Ks[nb + 1][r] = f2tf32(expf(k0.y - m_r));
        Ks[nb + 2][r] = f2tf32(expf(k0.z - m_r));
        Ks[nb + 3][r] = f2tf32(expf(k0.w - m_r));
        Ks[nb + 4][r] = f2tf32(expf(k1.x - m_r));
        Ks[nb + 5][r] = f2tf32(expf(k1.y - m_r));
        Ks[nb + 6][r] = f2tf32(expf(k1.z - m_r));
        Ks[nb + 7][r] = f2tf32(expf(k1.w - m_r));
        Vs[nb    ][r] = f2tf32(v0.x);
        Vs[nb + 1][r] = f2tf32(v0.y);
        Vs[nb + 2][r] = f2tf32(v0.z);
        Vs[nb + 3][r] = f2tf32(v0.w);
        Vs[nb + 4][r] = f2tf32(v1.x);
        Vs[nb + 5][r] = f2tf32(v1.y);
        Vs[nb + 6][r] = f2tf32(v1.z);
        Vs[nb + 7][r] = f2tf32(v1.w);
        __syncthreads();

        if (c + 1 < 8) {
            const float* krn = kr + (c + 1) * 32;
            const float* vrn = vr + (c + 1) * 32;
            k0 = *reinterpret_cast<const float4*>(krn);
            k1 = *reinterpret_cast<const float4*>(krn + 4);
            v0 = *reinterpret_cast<const float4*>(vrn);
            v1 = *reinterpret_cast<const float4*>(vrn + 4);
        }

#pragma unroll
        for (int ks = 0; ks < 32; ks += 8) {
            uint32_t af[2][4];
            uint32_t bf[2][2];
#pragma unroll
            for (int mt = 0; mt < 2; mt++) {
                const int mb = wm + mt * 16;
                af[mt][0] = Ks[ks + tg    ][mb + g];
                af[mt][1] = Ks[ks + tg    ][mb + g + 8];
                af[mt][2] = Ks[ks + tg + 4][mb + g];
                af[mt][3] = Ks[ks + tg + 4][mb + g + 8];
            }
#pragma unroll
            for (int nt = 0; nt < 2; nt++) {
                const int nbx = wn + nt * 8;
                bf[nt][0] = Vs[ks + tg    ][nbx + g];
                bf[nt][1] = Vs[ks + tg + 4][nbx + g];
            }
#pragma unroll
            for (int mt = 0; mt < 2; mt++)
#pragma unroll
                for (int nt = 0; nt < 2; nt++)
                    mma_tf32(acc[mt][nt], af[mt], bf[nt]);
        }
        __syncthreads();
    }

    float* cp = g_ctxp + ((long)bh * NSPLIT + split) * DH * DH;
#pragma unroll
    for (int mt = 0; mt < 2; mt++) {
        const int m = wm + mt * 16 + g;
        const float is0 = g_stats[b * DIM + h * DH + m].y;
        const float is8 = g_stats[b * DIM + h * DH + m + 8].y;
#pragma unroll
        for (int nt = 0; nt < 2; nt++) {
            const int n = wn + nt * 8 + 2 * tg;
            float2 o0 = {acc[mt][nt][0] * is0, acc[mt][nt][1] * is0};
            float2 o1 = {acc[mt][nt][2] * is8, acc[mt][nt][3] * is8};
            *reinterpret_cast<float2*>(&cp[(long)m * DH + n])       = o0;
            *reinterpret_cast<float2*>(&cp[(long)(m + 8) * DH + n]) = o1;
        }
    }
}

// ======================= parallel split reduce =============================
__global__ __launch_bounds__(256) void ctx_reduce()
{
    const int idx = blockIdx.x * 256 + threadIdx.x;
    const int bh = idx >> 12;
    const int i  = idx & 4095;
    float s = 0.0f;
#pragma unroll
    for (int sp = 0; sp < NSPLIT; sp++)
        s += g_ctxp[((long)bh * NSPLIT + sp) * DH * DH + i];
    g_ctx[(long)bh * DH * DH + i] = s;
}

// ======================= fold w_out into ctx ===============================
__global__ __launch_bounds__(256) void wctx_fold(const float* __restrict__ w_out)
{
    const int bh = blockIdx.x;
    const int b = bh / HEADS, h = bh % HEADS;
    __shared__ float cs[64][65];
    const int tid = threadIdx.x;

    const float* cp = g_ctx + (long)bh * DH * DH;
    for (int i = tid; i < DH * DH; i += 256) cs[i >> 6][i & 63] = cp[i];
    __syncthreads();

    float* outp = g_wctxT + (long)b * DIM * DIM + (long)(h * DH) * DIM;

    for (int cb = 0; cb < 2; cb++) {
        const int c = cb * 256 + tid;
        float w[64];
#pragma unroll
        for (int e = 0; e < 64; e++) w[e] = w_out[(h * DH + e) * DIM + c];
#pragma unroll 4
        for (int d = 0; d < 64; d++) {
            float s = 0.0f;
#pragma unroll
            for (int e = 0; e < 64; e++) s = fmaf(cs[d][e], w[e], s);
            outp[(long)d * DIM + c] = s * SCALE;
        }
    }
}

// ---------------------------------------------------------------------------
extern "C" void kernel_launch(void* const* d_in, const int* in_sizes, int n_in,
                              void* d_out, int out_size)
{
    const float* x      = (const float*)d_in[0];   // (B, 512, 4096)
    const float* w_qkv  = (const float*)d_in[1];   // (512, 1536)
    const float* w_out  = (const float*)d_in[2];   // (512, 512)
    const float* b_out  = (const float*)d_in[3];   // (512,)
    float* out = (float*)d_out;                    // (B, 512, 4096)

    float* qkv;
    float* xr;
    float* wkv;
    float* wctxT;
    float* wqT;
    float* M2;
    cudaGetSymbolAddress((void**)&qkv,   g_qkv);
    cudaGetSymbolAddress((void**)&xr,    g_xr);
    cudaGetSymbolAddress((void**)&wkv,   g_wkv);
    cudaGetSymbolAddress((void**)&wctxT, g_wctxT);
    cudaGetSymbolAddress((void**)&wqT,   g_wqT);
    cudaGetSymbolAddress((void**)&M2,    g_M2);

    cudaFuncSetAttribute(gemm_async, cudaFuncAttributeMaxDynamicSharedMemorySize, GA_SMEM);

    // 0) pre-round inputs (RNA tf32): x -> xr, w_kv slice -> wkv; wqT raw
    {
        const int n4 = BATCH * DIM * LSEQ / 4;
        rna_vec<<<(n4 + 255) / 256, 256>>>((const float4*)x, (float4*)xr, n4);
        rna_wkv<<<(DIM * FKV / 4) / 256, 256>>>(w_qkv);
        dim3 g(DIM / 32, DIM / 32, 1);
        transpose_k<<<g, 256>>>(w_qkv, wqT, DIM, DIM, F3);
    }

    // 1) k,v = W_kv^T @ x per batch  (async GEMM, 128-thr CTA, 2 CTA/SM)
    {
        dim3 grid(LSEQ / GA_BN, FKV / GA_BM, BATCH);
        gemm_async<<<grid, 128, GA_SMEM>>>(wkv, xr, qkv,
                                           FKV, LSEQ, LSEQ, DIM,
                                           0L, (long)DIM * LSEQ, (long)FKV * LSEQ,
                                           nullptr);
    }

    // 2) softmax stats per k row
    softmax_stats<<<BATCH * DIM, 256>>>();

    // 3) ctx partials via tensor cores with fused exp/normalize
    {
        dim3 grid(BATCH * HEADS, NSPLIT);
        ctx_partial_tc<<<grid, 256>>>();
    }

    // 3b) parallel reduce
    ctx_reduce<<<(BATCH * HEADS * DH * DH) / 256, 256>>>();

    // 4) fold w_out into ctx (includes SCALE)
    wctx_fold<<<BATCH * HEADS, 256>>>(w_out);

    // 5) M2 = wqT^T-fold (small; rounds output for the async GEMM)
    {
        dim3 grid(DIM / BN, DIM / BM, BATCH);
        gemm_tf32<<<grid, 256>>>(wqT, wctxT, M2,
                                 DIM, DIM, DIM, DIM,
                                 0L, (long)DIM * DIM, (long)DIM * DIM,
                                 nullptr, 1);
    }

    // 6) out = M2^T @ x + bias  (async GEMM, 128-thr CTA, 2 CTA/SM)
    {
        dim3 grid(LSEQ / GA_BN, DIM / GA_BM, BATCH);
        gemm_async<<<grid, 128, GA_SMEM>>>(M2, xr, out,
                                           DIM, LSEQ, LSEQ, DIM,
                                           (long)DIM * DIM, (long)DIM * LSEQ, (long)DIM * LSEQ,
                                           b_out);
    }
}